// round 1
// baseline (speedup 1.0000x reference)
#include <cuda_runtime.h>

#define NNODES 255
#define BATCH  256
#define MROWS  (NNODES * BATCH)   // 65280
#define LDA_A  256                // padded leading dim for dense adjacency
#define MAXF   400

// Scratch (no cudaMalloc allowed): ping-pong activation buffers in [N, B, F] layout
__device__ float g_buf0[MROWS * MAXF];   // ~99.6 MiB
__device__ float g_buf1[MROWS * MAXF];   // ~99.6 MiB
__device__ float g_adj[4 * NNODES * LDA_A];   // 4 densified COO operators, ~1 MiB

// ---------------------------------------------------------------------------
// Adjacency densification: A[r,c] = sum of vals over duplicate (r,c) edges
// (matches jax segment_sum semantics exactly).
// ---------------------------------------------------------------------------
__global__ void zero_adj_kernel(float* adj, int n) {
    int i = blockIdx.x * 256 + threadIdx.x;
    if (i < n) adj[i] = 0.0f;
}

__global__ void scatter_adj_kernel(const int* __restrict__ rows,
                                   const int* __restrict__ cols,
                                   const float* __restrict__ vals,
                                   int nnz, float* adj) {
    int e = blockIdx.x * 256 + threadIdx.x;
    if (e < nnz) {
        atomicAdd(&adj[rows[e] * LDA_A + cols[e]], vals[e]);
    }
}

// ---------------------------------------------------------------------------
// Layout transposes: H[B,N,2] <-> X[N,B,2]   (float2 per node)
// ---------------------------------------------------------------------------
__global__ void transpose_in_kernel(const float* __restrict__ H, float* __restrict__ X) {
    int i = blockIdx.x * 256 + threadIdx.x;          // over B*N
    if (i < BATCH * NNODES) {
        int b = i / NNODES, n = i % NNODES;
        const float2 v = reinterpret_cast<const float2*>(H)[i];
        reinterpret_cast<float2*>(X)[n * BATCH + b] = v;
    }
}

__global__ void transpose_out_kernel(const float* __restrict__ X, float* __restrict__ O) {
    int i = blockIdx.x * 256 + threadIdx.x;          // over B*N
    if (i < BATCH * NNODES) {
        int b = i / NNODES, n = i % NNODES;
        reinterpret_cast<float2*>(O)[i] = reinterpret_cast<const float2*>(X)[n * BATCH + b];
    }
}

// ---------------------------------------------------------------------------
// Generic fp32 SGEMM: C[M,N] = A[M,K] @ B[K,N]  (+ bias[col]) (+ relu)
// Tiles: 64x64x16, 256 threads, 4x4 per-thread microkernel.
// ---------------------------------------------------------------------------
template <bool RELU, bool BIAS>
__global__ __launch_bounds__(256)
void sgemm_kernel(const float* __restrict__ A, const float* __restrict__ B,
                  const float* __restrict__ bias, float* __restrict__ C,
                  int M, int N, int K, int lda, int ldb, int ldc) {
    __shared__ float As[16][65];   // [k][m], padded vs bank conflicts
    __shared__ float Bs[16][64];   // [k][n]

    const int tid = threadIdx.x;
    const int tx = tid & 15;       // 0..15 -> 4 cols each
    const int ty = tid >> 4;       // 0..15 -> 4 rows each
    const int row0 = blockIdx.y * 64;
    const int col0 = blockIdx.x * 64;

    float acc[4][4] = {};

    for (int k0 = 0; k0 < K; k0 += 16) {
        // Load A tile (64 rows x 16 k), coalesced along k within a row.
        #pragma unroll
        for (int i = 0; i < 4; i++) {
            int idx = tid + i * 256;
            int r = idx >> 4, c = idx & 15;
            int gr = row0 + r, gc = k0 + c;
            As[c][r] = (gr < M && gc < K) ? A[(long)gr * lda + gc] : 0.0f;
        }
        // Load B tile (16 k x 64 cols), fully coalesced.
        #pragma unroll
        for (int i = 0; i < 4; i++) {
            int idx = tid + i * 256;
            int r = idx >> 6, c = idx & 63;
            int gr = k0 + r, gc = col0 + c;
            Bs[r][c] = (gr < K && gc < N) ? B[(long)gr * ldb + gc] : 0.0f;
        }
        __syncthreads();

        #pragma unroll
        for (int k = 0; k < 16; k++) {
            float a[4], b[4];
            #pragma unroll
            for (int i = 0; i < 4; i++) a[i] = As[k][ty * 4 + i];
            #pragma unroll
            for (int j = 0; j < 4; j++) b[j] = Bs[k][tx * 4 + j];
            #pragma unroll
            for (int i = 0; i < 4; i++)
                #pragma unroll
                for (int j = 0; j < 4; j++)
                    acc[i][j] = fmaf(a[i], b[j], acc[i][j]);
        }
        __syncthreads();
    }

    #pragma unroll
    for (int i = 0; i < 4; i++) {
        int r = row0 + ty * 4 + i;
        if (r >= M) continue;
        #pragma unroll
        for (int j = 0; j < 4; j++) {
            int c = col0 + tx * 4 + j;
            if (c >= N) continue;
            float v = acc[i][j];
            if (BIAS) v += bias[c];
            if (RELU) v = fmaxf(v, 0.0f);
            C[(long)r * ldc + c] = v;
        }
    }
}

// ---------------------------------------------------------------------------
// Launch
//
// Inputs (metadata order):
//  0: H [256,255,2]
//  1-3:   sm_s rows/cols/vals     4-6:  sm_t
//  7-9:   sp_s                    10-12: sp_t
//  13..24: W0,b0, W1,b1, W2,b2, Wd0,bd0, Wd1,bd1, Wd2,bd2
// ---------------------------------------------------------------------------
extern "C" void kernel_launch(void* const* d_in, const int* in_sizes, int n_in,
                              void* d_out, int out_size) {
    const float* H = (const float*)d_in[0];

    float *buf0, *buf1, *adj;
    cudaGetSymbolAddress((void**)&buf0, g_buf0);
    cudaGetSymbolAddress((void**)&buf1, g_buf1);
    cudaGetSymbolAddress((void**)&adj,  g_adj);

    // Build the 4 dense adjacency operators.
    {
        int tot = 4 * NNODES * LDA_A;
        zero_adj_kernel<<<(tot + 255) / 256, 256>>>(adj, tot);
        // adj slot order: 0=sm_s, 1=sm_t, 2=sp_s, 3=sp_t
        for (int w = 0; w < 4; w++) {
            int base = 1 + 3 * w;
            int nnz = in_sizes[base];
            scatter_adj_kernel<<<(nnz + 255) / 256, 256>>>(
                (const int*)d_in[base], (const int*)d_in[base + 1],
                (const float*)d_in[base + 2], nnz,
                adj + (size_t)w * NNODES * LDA_A);
        }
    }

    // [B,N,2] -> [N,B,2]
    transpose_in_kernel<<<(BATCH * NNODES + 255) / 256, 256>>>(H, buf0);

    const int din_[6]  = {2, 400, 300, 100, 300, 400};
    const int dout_[6] = {400, 300, 100, 300, 400, 2};
    const int adjIdx[6] = {0, 0, 1, 3, 2, 2};  // sm_s, sm_s, sm_t, sp_t, sp_s, sp_s

    float* cur = buf0;   // activations [N, B, din]
    float* tmp = buf1;

    for (int l = 0; l < 6; l++) {
        const float* W    = (const float*)d_in[13 + 2 * l];
        const float* bias = (const float*)d_in[14 + 2 * l];
        const int di = din_[l], dl = dout_[l];

        // G1: tmp[65280, do] = cur[65280, di] @ W[di, do] + bias
        {
            dim3 grid((dl + 63) / 64, MROWS / 64);
            sgemm_kernel<false, true><<<grid, 256>>>(
                cur, W, bias, tmp, MROWS, dl, di, di, dl, dl);
        }
        // G2: cur[255, B*do] = relu( A[255,255] @ tmp[255, B*do] )
        {
            int Nw = BATCH * dl;
            dim3 grid((Nw + 63) / 64, (NNODES + 63) / 64);
            sgemm_kernel<true, false><<<grid, 256>>>(
                adj + (size_t)adjIdx[l] * NNODES * LDA_A, tmp, nullptr, cur,
                NNODES, Nw, NNODES, LDA_A, Nw, Nw);
        }
    }

    // cur == buf0 after an even number of layers: [N,B,2] -> out [B,N,2]
    transpose_out_kernel<<<(BATCH * NNODES + 255) / 256, 256>>>(cur, (float*)d_out);
}

// round 2
// speedup vs baseline: 1.6567x; 1.6567x over previous
#include <cuda_runtime.h>

#define NNODES 255
#define BATCH  256
#define MROWS  (NNODES * BATCH)   // 65280
#define MAXF   400
#define ELL_CAP 64
#define MAX_NNZ 2048

// Scratch (no cudaMalloc allowed)
__device__ float g_buf0[MROWS * MAXF];               // ~99.6 MiB
__device__ float g_buf1[MROWS * MAXF];               // ~99.6 MiB
__device__ float g_ell_vals[4 * NNODES * ELL_CAP];
__device__ int   g_ell_cols[4 * NNODES * ELL_CAP];
__device__ int   g_ell_cnt [4 * NNODES];

// ---------------------------------------------------------------------------
// ELL build. Deterministic slot = #{earlier edges with same row}, so the
// accumulation order in the SpMM is fixed across replays (and duplicate
// (r,c) pairs sum exactly like segment_sum).
// ---------------------------------------------------------------------------
__global__ void zero_cnt_kernel(int* cnt, int n) {
    int i = blockIdx.x * 256 + threadIdx.x;
    if (i < n) cnt[i] = 0;
}

__global__ void ell_build_kernel(const int* __restrict__ rows,
                                 const int* __restrict__ cols,
                                 const float* __restrict__ vals,
                                 int nnz, float* evals, int* ecols, int* cnt) {
    __shared__ int srows[MAX_NNZ];
    int tid = threadIdx.x;
    int nld = nnz < MAX_NNZ ? nnz : MAX_NNZ;
    for (int i = tid; i < nld; i += blockDim.x) srows[i] = rows[i];
    __syncthreads();

    int e = blockIdx.x * blockDim.x + tid;
    if (e < nnz) {
        int r = (e < MAX_NNZ) ? srows[e] : rows[e];
        int slot = 0;
        for (int k = 0; k < e && k < MAX_NNZ; k++) slot += (srows[k] == r);
        if (slot < ELL_CAP) {
            evals[r * ELL_CAP + slot] = vals[e];
            ecols[r * ELL_CAP + slot] = cols[e];
            atomicMax(&cnt[r], slot + 1);
        }
    }
}

// ---------------------------------------------------------------------------
// Sparse G2: Y[r, f] = relu( sum_j val[r,j] * X[col[r,j], f] ), f in [0, Nw)
// X, Y are [NNODES, Nw] row-major; float4 vectorized, coalesced in f.
// ---------------------------------------------------------------------------
__global__ __launch_bounds__(256)
void spmm_ell_kernel(const float* __restrict__ evals, const int* __restrict__ ecols,
                     const int* __restrict__ cnt,
                     const float* __restrict__ X, float* __restrict__ Y, int Nw) {
    const int r = blockIdx.y;
    const int f = (blockIdx.x * 256 + threadIdx.x) * 4;
    const int n = cnt[r];

    __shared__ float sv[ELL_CAP];
    __shared__ int   sc[ELL_CAP];
    if (threadIdx.x < n) {
        sv[threadIdx.x] = evals[r * ELL_CAP + threadIdx.x];
        sc[threadIdx.x] = ecols[r * ELL_CAP + threadIdx.x];
    }
    __syncthreads();

    if (f >= Nw) return;

    float4 acc0 = make_float4(0.f, 0.f, 0.f, 0.f);
    int j = 0;
    // 2-way unroll: two independent load streams, deterministic final sum
    // (acc0 holds even slots, acc1 odd slots; combined as acc0+acc1 would
    //  reorder sums, so fold pairwise in fixed order instead).
    for (; j + 1 < n; j += 2) {
        float a0 = sv[j], a1 = sv[j + 1];
        float4 x0 = *reinterpret_cast<const float4*>(X + (size_t)sc[j] * Nw + f);
        float4 x1 = *reinterpret_cast<const float4*>(X + (size_t)sc[j + 1] * Nw + f);
        acc0.x = fmaf(a0, x0.x, acc0.x); acc0.x = fmaf(a1, x1.x, acc0.x);
        acc0.y = fmaf(a0, x0.y, acc0.y); acc0.y = fmaf(a1, x1.y, acc0.y);
        acc0.z = fmaf(a0, x0.z, acc0.z); acc0.z = fmaf(a1, x1.z, acc0.z);
        acc0.w = fmaf(a0, x0.w, acc0.w); acc0.w = fmaf(a1, x1.w, acc0.w);
    }
    if (j < n) {
        float a0 = sv[j];
        float4 x0 = *reinterpret_cast<const float4*>(X + (size_t)sc[j] * Nw + f);
        acc0.x = fmaf(a0, x0.x, acc0.x);
        acc0.y = fmaf(a0, x0.y, acc0.y);
        acc0.z = fmaf(a0, x0.z, acc0.z);
        acc0.w = fmaf(a0, x0.w, acc0.w);
    }
    acc0.x = fmaxf(acc0.x, 0.f);
    acc0.y = fmaxf(acc0.y, 0.f);
    acc0.z = fmaxf(acc0.z, 0.f);
    acc0.w = fmaxf(acc0.w, 0.f);
    *reinterpret_cast<float4*>(Y + (size_t)r * Nw + f) = acc0;
}

// ---------------------------------------------------------------------------
// Layout transposes: H[B,N,2] <-> X[N,B,2]
// ---------------------------------------------------------------------------
__global__ void transpose_in_kernel(const float* __restrict__ H, float* __restrict__ X) {
    int i = blockIdx.x * 256 + threadIdx.x;
    if (i < BATCH * NNODES) {
        int b = i / NNODES, n = i % NNODES;
        const float2 v = reinterpret_cast<const float2*>(H)[i];
        reinterpret_cast<float2*>(X)[n * BATCH + b] = v;
    }
}

__global__ void transpose_out_kernel(const float* __restrict__ X, float* __restrict__ O) {
    int i = blockIdx.x * 256 + threadIdx.x;
    if (i < BATCH * NNODES) {
        int b = i / NNODES, n = i % NNODES;
        reinterpret_cast<float2*>(O)[i] = reinterpret_cast<const float2*>(X)[n * BATCH + b];
    }
}

// ---------------------------------------------------------------------------
// fp32 SGEMM: C[M,N] = A[M,K] @ B[K,N] + bias[col]   (G1 projections)
// 64x64x16 tiles, 256 threads, 4x4 microkernel.
// ---------------------------------------------------------------------------
template <bool RELU, bool BIAS>
__global__ __launch_bounds__(256)
void sgemm_kernel(const float* __restrict__ A, const float* __restrict__ B,
                  const float* __restrict__ bias, float* __restrict__ C,
                  int M, int N, int K, int lda, int ldb, int ldc) {
    __shared__ float As[16][65];
    __shared__ float Bs[16][64];

    const int tid = threadIdx.x;
    const int tx = tid & 15;
    const int ty = tid >> 4;
    const int row0 = blockIdx.y * 64;
    const int col0 = blockIdx.x * 64;

    float acc[4][4] = {};

    for (int k0 = 0; k0 < K; k0 += 16) {
        #pragma unroll
        for (int i = 0; i < 4; i++) {
            int idx = tid + i * 256;
            int r = idx >> 4, c = idx & 15;
            int gr = row0 + r, gc = k0 + c;
            As[c][r] = (gr < M && gc < K) ? A[(long)gr * lda + gc] : 0.0f;
        }
        #pragma unroll
        for (int i = 0; i < 4; i++) {
            int idx = tid + i * 256;
            int r = idx >> 6, c = idx & 63;
            int gr = k0 + r, gc = col0 + c;
            Bs[r][c] = (gr < K && gc < N) ? B[(long)gr * ldb + gc] : 0.0f;
        }
        __syncthreads();

        #pragma unroll
        for (int k = 0; k < 16; k++) {
            float a[4], b[4];
            #pragma unroll
            for (int i = 0; i < 4; i++) a[i] = As[k][ty * 4 + i];
            #pragma unroll
            for (int j = 0; j < 4; j++) b[j] = Bs[k][tx * 4 + j];
            #pragma unroll
            for (int i = 0; i < 4; i++)
                #pragma unroll
                for (int j = 0; j < 4; j++)
                    acc[i][j] = fmaf(a[i], b[j], acc[i][j]);
        }
        __syncthreads();
    }

    #pragma unroll
    for (int i = 0; i < 4; i++) {
        int r = row0 + ty * 4 + i;
        if (r >= M) continue;
        #pragma unroll
        for (int j = 0; j < 4; j++) {
            int c = col0 + tx * 4 + j;
            if (c >= N) continue;
            float v = acc[i][j];
            if (BIAS) v += bias[c];
            if (RELU) v = fmaxf(v, 0.0f);
            C[(long)r * ldc + c] = v;
        }
    }
}

// ---------------------------------------------------------------------------
// Launch
// ---------------------------------------------------------------------------
extern "C" void kernel_launch(void* const* d_in, const int* in_sizes, int n_in,
                              void* d_out, int out_size) {
    const float* H = (const float*)d_in[0];

    float *buf0, *buf1, *evals;
    int *ecols, *ecnt;
    cudaGetSymbolAddress((void**)&buf0,  g_buf0);
    cudaGetSymbolAddress((void**)&buf1,  g_buf1);
    cudaGetSymbolAddress((void**)&evals, g_ell_vals);
    cudaGetSymbolAddress((void**)&ecols, g_ell_cols);
    cudaGetSymbolAddress((void**)&ecnt,  g_ell_cnt);

    // Build 4 ELL operators: 0=sm_s, 1=sm_t, 2=sp_s, 3=sp_t
    zero_cnt_kernel<<<(4 * NNODES + 255) / 256, 256>>>(ecnt, 4 * NNODES);
    for (int w = 0; w < 4; w++) {
        int base = 1 + 3 * w;
        int nnz = in_sizes[base];
        ell_build_kernel<<<(nnz + 255) / 256, 256>>>(
            (const int*)d_in[base], (const int*)d_in[base + 1],
            (const float*)d_in[base + 2], nnz,
            evals + (size_t)w * NNODES * ELL_CAP,
            ecols + (size_t)w * NNODES * ELL_CAP,
            ecnt + w * NNODES);
    }

    // [B,N,2] -> [N,B,2]
    transpose_in_kernel<<<(BATCH * NNODES + 255) / 256, 256>>>(H, buf0);

    const int din_[6]  = {2, 400, 300, 100, 300, 400};
    const int dout_[6] = {400, 300, 100, 300, 400, 2};
    const int adjIdx[6] = {0, 0, 1, 3, 2, 2};  // sm_s, sm_s, sm_t, sp_t, sp_s, sp_s

    float* cur = buf0;   // activations [N, B, din]
    float* tmp = buf1;

    for (int l = 0; l < 6; l++) {
        const float* W    = (const float*)d_in[13 + 2 * l];
        const float* bias = (const float*)d_in[14 + 2 * l];
        const int di = din_[l], dl = dout_[l];

        // G1: tmp[65280, do] = cur[65280, di] @ W[di, do] + bias
        {
            dim3 grid((dl + 63) / 64, MROWS / 64);
            sgemm_kernel<false, true><<<grid, 256>>>(
                cur, W, bias, tmp, MROWS, dl, di, di, dl, dl);
        }
        // G2 (sparse): cur[255, B*do] = relu( A_ell @ tmp )
        {
            int Nw = BATCH * dl;
            dim3 grid((Nw + 1023) / 1024, NNODES);
            spmm_ell_kernel<<<grid, 256>>>(
                evals + (size_t)adjIdx[l] * NNODES * ELL_CAP,
                ecols + (size_t)adjIdx[l] * NNODES * ELL_CAP,
                ecnt + adjIdx[l] * NNODES,
                tmp, cur, Nw);
        }
    }

    transpose_out_kernel<<<(BATCH * NNODES + 255) / 256, 256>>>(cur, (float*)d_out);
}

// round 5
// speedup vs baseline: 2.7503x; 1.6601x over previous
#include <cuda_runtime.h>
#include <cuda_bf16.h>
#include <cstdint>

#define NNODES 255
#define BATCH  256
#define MROWS  (NNODES * BATCH)   // 65280
#define ELL_CAP 64
#define MAX_NNZ 2048
#define KP_MAX  416

// ---------------------------------------------------------------------------
// Scratch (no cudaMalloc allowed)
// ---------------------------------------------------------------------------
__device__ __align__(128) float          g_y   [MROWS * 400];        // fp32 GEMM out
__device__ __align__(128) float          g_y2  [MROWS * 400];        // fp32 (layer5 input)
__device__ __align__(128) __nv_bfloat16  g_xh  [MROWS * KP_MAX];     // split activations hi
__device__ __align__(128) __nv_bfloat16  g_xl  [MROWS * KP_MAX];     // split activations lo
__device__ __align__(128) __nv_bfloat16  g_wth [4 * 400 * KP_MAX];   // W^T hi, padded K
__device__ __align__(128) __nv_bfloat16  g_wtl [4 * 400 * KP_MAX];   // W^T lo
__device__ __align__(128) float          g_sa  [MROWS * 2];
__device__ __align__(128) float          g_sb  [MROWS * 2];
__device__ float g_ell_vals[4 * NNODES * ELL_CAP];
__device__ int   g_ell_cols[4 * NNODES * ELL_CAP];
__device__ int   g_ell_cnt [4 * NNODES];

// ---------------------------------------------------------------------------
// PTX helpers (family-neutral: mma.sync / ldmatrix / cp.async)
// ---------------------------------------------------------------------------
__device__ __forceinline__ uint32_t smem_u32(const void* p) {
    uint32_t a;
    asm("{ .reg .u64 t; cvta.to.shared.u64 t, %1; cvt.u32.u64 %0, t; }"
        : "=r"(a) : "l"(p));
    return a;
}

__device__ __forceinline__ void cp16(uint32_t dst, const void* src, uint32_t bytes) {
    asm volatile("cp.async.cg.shared.global [%0], [%1], 16, %2;"
                 :: "r"(dst), "l"(src), "r"(bytes) : "memory");
}
#define CP_COMMIT() asm volatile("cp.async.commit_group;" ::: "memory")
#define CP_WAIT(n)  asm volatile("cp.async.wait_group %0;" :: "n"(n) : "memory")

__device__ __forceinline__ void ldsm4(uint32_t* r, uint32_t addr) {
    asm volatile("ldmatrix.sync.aligned.m8n8.x4.shared.b16 {%0,%1,%2,%3}, [%4];"
                 : "=r"(r[0]), "=r"(r[1]), "=r"(r[2]), "=r"(r[3]) : "r"(addr));
}
__device__ __forceinline__ void ldsm2(uint32_t* r, uint32_t addr) {
    asm volatile("ldmatrix.sync.aligned.m8n8.x2.shared.b16 {%0,%1}, [%2];"
                 : "=r"(r[0]), "=r"(r[1]) : "r"(addr));
}
__device__ __forceinline__ void mma16816(float* c, const uint32_t* a, const uint32_t* b) {
    asm volatile("mma.sync.aligned.m16n8k16.row.col.f32.bf16.bf16.f32 "
                 "{%0,%1,%2,%3}, {%4,%5,%6,%7}, {%8,%9}, {%0,%1,%2,%3};"
                 : "+f"(c[0]), "+f"(c[1]), "+f"(c[2]), "+f"(c[3])
                 : "r"(a[0]), "r"(a[1]), "r"(a[2]), "r"(a[3]), "r"(b[0]), "r"(b[1]));
}

// ---------------------------------------------------------------------------
// bf16x3 HMMA GEMM: Y[M=65280, Nfull] = Ah@Bh^T + Ah@Bl^T + Al@Bh^T + bias
//   A*: [M, Kp] bf16 row-major, zero K-pad; B*: [Nfull, Kp] bf16 row-major.
//   CTA tile 128x128x32, 256 threads, warp tile 64x32, cp.async double buffer.
// ---------------------------------------------------------------------------
#define BM 128
#define BN 128
#define BK 32
#define LDT 40                      // padded SMEM row stride (bf16 elems)
#define TILE_B (128 * LDT * 2)      // 10240 bytes per matrix tile
#define STAGE_B (4 * TILE_B)        // Ah, Al, Bh, Bl

__global__ __launch_bounds__(256)
void gemm_bf16x3_mma(const __nv_bfloat16* __restrict__ Ah,
                     const __nv_bfloat16* __restrict__ Al,
                     const __nv_bfloat16* __restrict__ Bh,
                     const __nv_bfloat16* __restrict__ Bl,
                     const float* __restrict__ bias,
                     float* __restrict__ Y,
                     int Nfull, int Kp) {
    extern __shared__ __align__(128) char smem[];
    const uint32_t sb = smem_u32(smem);

    const int tid  = threadIdx.x;
    const int lane = tid & 31;
    const int wid  = tid >> 5;
    const int wm   = wid & 1;              // 0..1 -> m offset 0/64
    const int wn   = wid >> 1;             // 0..3 -> n offset 0/32/64/96
    const int m0   = blockIdx.y * BM;
    const int n0   = blockIdx.x * BN;

    const int nblk = Kp >> 5;              // BK=32 chunks (Kp % 32 == 0)

    // ---- async tile loader: 2048 x 16B chunks per stage, 8 per thread ----
    auto load_stage = [&](int blk, int s) {
        const int k0 = blk << 5;
        const uint32_t sdst = sb + s * STAGE_B;
        #pragma unroll
        for (int i = 0; i < 8; i++) {
            const int idx = i * 256 + tid;          // 0..2047
            const int mat = idx >> 9;               // 0=Ah 1=Al 2=Bh 3=Bl
            const int c   = idx & 511;
            const int row = c >> 2;
            const int seg = c & 3;
            const uint32_t dst = sdst + mat * TILE_B + (row * LDT + seg * 8) * 2;
            if (mat < 2) {
                const __nv_bfloat16* src = (mat == 0 ? Ah : Al);
                cp16(dst, src + (size_t)(m0 + row) * Kp + k0 + seg * 8, 16);
            } else {
                const __nv_bfloat16* src = (mat == 2 ? Bh : Bl);
                const int gr = n0 + row;
                const int ok = gr < Nfull;
                cp16(dst, src + (size_t)(ok ? gr : 0) * Kp + k0 + seg * 8, ok ? 16 : 0);
            }
        }
        CP_COMMIT();
    };

    float acc[4][4][4];
    #pragma unroll
    for (int i = 0; i < 4; i++)
        #pragma unroll
        for (int j = 0; j < 4; j++)
            #pragma unroll
            for (int q = 0; q < 4; q++) acc[i][j][q] = 0.0f;

    load_stage(0, 0);

    for (int blk = 0; blk < nblk; blk++) {
        const int s = blk & 1;
        __syncthreads();                    // everyone done with stage s's old data
        if (blk + 1 < nblk) {
            load_stage(blk + 1, s ^ 1);
            CP_WAIT(1);
        } else {
            CP_WAIT(0);
        }
        __syncthreads();

        const uint32_t stage = sb + s * STAGE_B;
        #pragma unroll
        for (int ks = 0; ks < BK; ks += 16) {
            uint32_t ah[4][4], al[4][4], bh[4][2], bl[4][2];
            const int arow = wm * 64 + (lane & 15);
            const int akoff = ks + ((lane >> 4) << 3);
            #pragma unroll
            for (int mi = 0; mi < 4; mi++) {
                const uint32_t off = ((arow + mi * 16) * LDT + akoff) * 2;
                ldsm4(ah[mi], stage + off);
                ldsm4(al[mi], stage + TILE_B + off);
            }
            const int brow = wn * 32 + (lane & 7);
            const int bkoff = ks + (((lane >> 3) & 1) << 3);
            #pragma unroll
            for (int ni = 0; ni < 4; ni++) {
                const uint32_t off = ((brow + ni * 8) * LDT + bkoff) * 2;
                ldsm2(bh[ni], stage + 2 * TILE_B + off);
                ldsm2(bl[ni], stage + 3 * TILE_B + off);
            }
            #pragma unroll
            for (int mi = 0; mi < 4; mi++)
                #pragma unroll
                for (int ni = 0; ni < 4; ni++) {
                    mma16816(acc[mi][ni], ah[mi], bh[ni]);
                    mma16816(acc[mi][ni], ah[mi], bl[ni]);
                    mma16816(acc[mi][ni], al[mi], bh[ni]);
                }
        }
    }

    // ---- epilogue: direct global stores + bias ----
    #pragma unroll
    for (int ni = 0; ni < 4; ni++) {
        const int gc = n0 + wn * 32 + ni * 8 + (lane & 3) * 2;
        if (gc >= Nfull) continue;
        const float b0 = bias[gc], b1 = bias[gc + 1];
        #pragma unroll
        for (int mi = 0; mi < 4; mi++) {
            const int gr = m0 + wm * 64 + mi * 16 + (lane >> 2);
            float2 v0 = make_float2(acc[mi][ni][0] + b0, acc[mi][ni][1] + b1);
            float2 v1 = make_float2(acc[mi][ni][2] + b0, acc[mi][ni][3] + b1);
            *(float2*)(Y + (size_t)gr * Nfull + gc) = v0;
            *(float2*)(Y + (size_t)(gr + 8) * Nfull + gc) = v1;
        }
    }
}

// ---------------------------------------------------------------------------
// Weight prep: Wt_h/Wt_l[n, k] = split(W[k, n]), zero-padded k in [K, Kp)
// ---------------------------------------------------------------------------
__global__ void wt_split_kernel(const float* __restrict__ W, int K, int N, int Kp,
                                __nv_bfloat16* __restrict__ wh,
                                __nv_bfloat16* __restrict__ wl) {
    int i = blockIdx.x * 256 + threadIdx.x;
    if (i >= N * Kp) return;
    int n = i / Kp, k = i - n * Kp;
    float v = (k < K) ? W[(size_t)k * N + n] : 0.0f;
    __nv_bfloat16 h = __float2bfloat16(v);
    wh[i] = h;
    wl[i] = __float2bfloat16(v - __bfloat162float(h));
}

// ---------------------------------------------------------------------------
// ELL build (all 4 operators, one launch; deterministic slot order)
// ---------------------------------------------------------------------------
__global__ void ell_build4_kernel(const int* r0, const int* c0, const float* v0, int n0_,
                                  const int* r1, const int* c1, const float* v1, int n1_,
                                  const int* r2, const int* c2, const float* v2, int n2_,
                                  const int* r3, const int* c3, const float* v3, int n3_,
                                  float* evals, int* ecols, int* cnt) {
    const int w = blockIdx.y;
    const int* rows = w == 0 ? r0 : w == 1 ? r1 : w == 2 ? r2 : r3;
    const int* cols = w == 0 ? c0 : w == 1 ? c1 : w == 2 ? c2 : c3;
    const float* vals = w == 0 ? v0 : w == 1 ? v1 : w == 2 ? v2 : v3;
    const int nnz = w == 0 ? n0_ : w == 1 ? n1_ : w == 2 ? n2_ : n3_;
    float* ev = evals + (size_t)w * NNODES * ELL_CAP;
    int* ec = ecols + (size_t)w * NNODES * ELL_CAP;
    int* cn = cnt + w * NNODES;

    __shared__ int srows[MAX_NNZ];
    const int tid = threadIdx.x;
    const int nld = nnz < MAX_NNZ ? nnz : MAX_NNZ;
    for (int i = tid; i < nld; i += blockDim.x) srows[i] = rows[i];
    __syncthreads();

    const int e = blockIdx.x * blockDim.x + tid;
    if (e < nnz) {
        const int r = (e < MAX_NNZ) ? srows[e] : rows[e];
        int slot = 0;
        for (int k = 0; k < e && k < MAX_NNZ; k++) slot += (srows[k] == r);
        if (slot < ELL_CAP) {
            ev[r * ELL_CAP + slot] = vals[e];
            ec[r * ELL_CAP + slot] = cols[e];
            atomicMax(&cn[r], slot + 1);
        }
    }
}

__global__ void zero_cnt_kernel(int* cnt, int n) {
    int i = blockIdx.x * 256 + threadIdx.x;
    if (i < n) cnt[i] = 0;
}

// ---------------------------------------------------------------------------
// SpMM: out[r,b,f] = relu( sum_j val_j * Y[(c_j*256+b)*do + f] )
// ---------------------------------------------------------------------------
__global__ __launch_bounds__(256)
void spmm_split_kernel(const float* __restrict__ evals, const int* __restrict__ ecols,
                       const int* __restrict__ cnt, const float* __restrict__ Y,
                       int do_, int kp,
                       __nv_bfloat16* __restrict__ xh, __nv_bfloat16* __restrict__ xl) {
    const int r = blockIdx.y;
    const int n = cnt[r];
    __shared__ float sv[ELL_CAP];
    __shared__ int   sc[ELL_CAP];
    if (threadIdx.x < n) {
        sv[threadIdx.x] = evals[r * ELL_CAP + threadIdx.x];
        sc[threadIdx.x] = ecols[r * ELL_CAP + threadIdx.x];
    }
    __syncthreads();

    const int nF4 = kp >> 2;
    const int p = blockIdx.x * 256 + threadIdx.x;
    if (p >= BATCH * nF4) return;
    const int b = p / nF4, f = (p - b * nF4) * 4;
    const size_t obase = ((size_t)r * BATCH + b) * kp + f;

    if (f >= do_) {
        *(uint2*)(xh + obase) = make_uint2(0, 0);
        *(uint2*)(xl + obase) = make_uint2(0, 0);
        return;
    }
    float4 acc = make_float4(0.f, 0.f, 0.f, 0.f);
    for (int j = 0; j < n; j++) {
        const float a = sv[j];
        const float4 x = *(const float4*)(Y + ((size_t)sc[j] * BATCH + b) * do_ + f);
        acc.x = fmaf(a, x.x, acc.x);
        acc.y = fmaf(a, x.y, acc.y);
        acc.z = fmaf(a, x.z, acc.z);
        acc.w = fmaf(a, x.w, acc.w);
    }
    acc.x = fmaxf(acc.x, 0.f); acc.y = fmaxf(acc.y, 0.f);
    acc.z = fmaxf(acc.z, 0.f); acc.w = fmaxf(acc.w, 0.f);

    __nv_bfloat162 h01 = __floats2bfloat162_rn(acc.x, acc.y);
    __nv_bfloat162 h23 = __floats2bfloat162_rn(acc.z, acc.w);
    float2 h01f = __bfloat1622float2(h01);
    float2 h23f = __bfloat1622float2(h23);
    __nv_bfloat162 l01 = __floats2bfloat162_rn(acc.x - h01f.x, acc.y - h01f.y);
    __nv_bfloat162 l23 = __floats2bfloat162_rn(acc.z - h23f.x, acc.w - h23f.y);
    uint2 uh, ul;
    uh.x = *(uint32_t*)&h01; uh.y = *(uint32_t*)&h23;
    ul.x = *(uint32_t*)&l01; ul.y = *(uint32_t*)&l23;
    *(uint2*)(xh + obase) = uh;
    *(uint2*)(xl + obase) = ul;
}

__global__ __launch_bounds__(256)
void spmm_f32_v4_kernel(const float* __restrict__ evals, const int* __restrict__ ecols,
                        const int* __restrict__ cnt, const float* __restrict__ Y,
                        int do_, float* __restrict__ out) {
    const int r = blockIdx.y;
    const int n = cnt[r];
    __shared__ float sv[ELL_CAP];
    __shared__ int   sc[ELL_CAP];
    if (threadIdx.x < n) {
        sv[threadIdx.x] = evals[r * ELL_CAP + threadIdx.x];
        sc[threadIdx.x] = ecols[r * ELL_CAP + threadIdx.x];
    }
    __syncthreads();
    const int nF4 = do_ >> 2;
    const int p = blockIdx.x * 256 + threadIdx.x;
    if (p >= BATCH * nF4) return;
    const int b = p / nF4, f = (p - b * nF4) * 4;
    float4 acc = make_float4(0.f, 0.f, 0.f, 0.f);
    for (int j = 0; j < n; j++) {
        const float a = sv[j];
        const float4 x = *(const float4*)(Y + ((size_t)sc[j] * BATCH + b) * do_ + f);
        acc.x = fmaf(a, x.x, acc.x);
        acc.y = fmaf(a, x.y, acc.y);
        acc.z = fmaf(a, x.z, acc.z);
        acc.w = fmaf(a, x.w, acc.w);
    }
    acc.x = fmaxf(acc.x, 0.f); acc.y = fmaxf(acc.y, 0.f);
    acc.z = fmaxf(acc.z, 0.f); acc.w = fmaxf(acc.w, 0.f);
    *(float4*)(out + ((size_t)r * BATCH + b) * do_ + f) = acc;
}

__global__ __launch_bounds__(256)
void spmm_f32_v2_kernel(const float* __restrict__ evals, const int* __restrict__ ecols,
                        const int* __restrict__ cnt, const float* __restrict__ Y,
                        int do_, float* __restrict__ out) {
    const int r = blockIdx.y;
    const int n = cnt[r];
    __shared__ float sv[ELL_CAP];
    __shared__ int   sc[ELL_CAP];
    if (threadIdx.x < n) {
        sv[threadIdx.x] = evals[r * ELL_CAP + threadIdx.x];
        sc[threadIdx.x] = ecols[r * ELL_CAP + threadIdx.x];
    }
    __syncthreads();
    const int nF2 = do_ >> 1;
    const int p = blockIdx.x * 256 + threadIdx.x;
    if (p >= BATCH * nF2) return;
    const int b = p / nF2, f = (p - b * nF2) * 2;
    float2 acc = make_float2(0.f, 0.f);
    for (int j = 0; j < n; j++) {
        const float a = sv[j];
        const float2 x = *(const float2*)(Y + ((size_t)sc[j] * BATCH + b) * do_ + f);
        acc.x = fmaf(a, x.x, acc.x);
        acc.y = fmaf(a, x.y, acc.y);
    }
    acc.x = fmaxf(acc.x, 0.f); acc.y = fmaxf(acc.y, 0.f);
    *(float2*)(out + ((size_t)r * BATCH + b) * do_ + f) = acc;
}

// ---------------------------------------------------------------------------
// Transposes: H[B,N,2] <-> X[N,B,2]
// ---------------------------------------------------------------------------
__global__ void transpose_in_kernel(const float* __restrict__ H, float* __restrict__ X) {
    int i = blockIdx.x * 256 + threadIdx.x;
    if (i < BATCH * NNODES) {
        int b = i / NNODES, n = i % NNODES;
        reinterpret_cast<float2*>(X)[n * BATCH + b] =
            reinterpret_cast<const float2*>(H)[i];
    }
}

__global__ void transpose_out_kernel(const float* __restrict__ X, float* __restrict__ O) {
    int i = blockIdx.x * 256 + threadIdx.x;
    if (i < BATCH * NNODES) {
        int b = i / NNODES, n = i % NNODES;
        reinterpret_cast<float2*>(O)[i] =
            reinterpret_cast<const float2*>(X)[n * BATCH + b];
    }
}

// ---------------------------------------------------------------------------
// fp32 SGEMM (layers 0 and 5): C = A@B + bias
// ---------------------------------------------------------------------------
__global__ __launch_bounds__(256)
void sgemm_kernel(const float* __restrict__ A, const float* __restrict__ B,
                  const float* __restrict__ bias, float* __restrict__ C,
                  int M, int N, int K, int lda, int ldb, int ldc) {
    __shared__ float As[16][65];
    __shared__ float Bs[16][64];
    const int tid = threadIdx.x;
    const int tx = tid & 15, ty = tid >> 4;
    const int row0 = blockIdx.y * 64, col0 = blockIdx.x * 64;
    float acc[4][4] = {};
    for (int k0 = 0; k0 < K; k0 += 16) {
        #pragma unroll
        for (int i = 0; i < 4; i++) {
            int idx = tid + i * 256;
            int r = idx >> 4, c = idx & 15;
            int gr = row0 + r, gc = k0 + c;
            As[c][r] = (gr < M && gc < K) ? A[(size_t)gr * lda + gc] : 0.0f;
        }
        #pragma unroll
        for (int i = 0; i < 4; i++) {
            int idx = tid + i * 256;
            int r = idx >> 6, c = idx & 63;
            int gr = k0 + r, gc = col0 + c;
            Bs[r][c] = (gr < K && gc < N) ? B[(size_t)gr * ldb + gc] : 0.0f;
        }
        __syncthreads();
        #pragma unroll
        for (int k = 0; k < 16; k++) {
            float a[4], b[4];
            #pragma unroll
            for (int i = 0; i < 4; i++) a[i] = As[k][ty * 4 + i];
            #pragma unroll
            for (int j = 0; j < 4; j++) b[j] = Bs[k][tx * 4 + j];
            #pragma unroll
            for (int i = 0; i < 4; i++)
                #pragma unroll
                for (int j = 0; j < 4; j++)
                    acc[i][j] = fmaf(a[i], b[j], acc[i][j]);
        }
        __syncthreads();
    }
    #pragma unroll
    for (int i = 0; i < 4; i++) {
        int r = row0 + ty * 4 + i;
        if (r >= M) continue;
        #pragma unroll
        for (int j = 0; j < 4; j++) {
            int c = col0 + tx * 4 + j;
            if (c >= N) continue;
            C[(size_t)r * ldc + c] = acc[i][j] + bias[c];
        }
    }
}

// ---------------------------------------------------------------------------
// Launch
// ---------------------------------------------------------------------------
extern "C" void kernel_launch(void* const* d_in, const int* in_sizes, int n_in,
                              void* d_out, int out_size) {
    const float* H = (const float*)d_in[0];

    float *y, *y2, *sa, *sbuf, *evals;
    __nv_bfloat16 *xh, *xl, *wth, *wtl;
    int *ecols, *ecnt;
    cudaGetSymbolAddress((void**)&y,    g_y);
    cudaGetSymbolAddress((void**)&y2,   g_y2);
    cudaGetSymbolAddress((void**)&xh,   g_xh);
    cudaGetSymbolAddress((void**)&xl,   g_xl);
    cudaGetSymbolAddress((void**)&wth,  g_wth);
    cudaGetSymbolAddress((void**)&wtl,  g_wtl);
    cudaGetSymbolAddress((void**)&sa,   g_sa);
    cudaGetSymbolAddress((void**)&sbuf, g_sb);
    cudaGetSymbolAddress((void**)&evals, g_ell_vals);
    cudaGetSymbolAddress((void**)&ecols, g_ell_cols);
    cudaGetSymbolAddress((void**)&ecnt,  g_ell_cnt);

    const int SMEM_GEMM = 2 * STAGE_B;   // 81920
    cudaFuncSetAttribute(gemm_bf16x3_mma,
                         cudaFuncAttributeMaxDynamicSharedMemorySize, SMEM_GEMM);

    // Tensor layers l=1..4: (K, N, Kp multiple of 32, weight input idx)
    const int tK[4]  = {400, 300, 100, 300};
    const int tN[4]  = {300, 100, 300, 400};
    const int tKp[4] = {416, 320, 128, 320};
    const int tW[4]  = {15, 17, 19, 21};

    for (int t = 0; t < 4; t++) {
        int tot = tN[t] * tKp[t];
        wt_split_kernel<<<(tot + 255) / 256, 256>>>(
            (const float*)d_in[tW[t]], tK[t], tN[t], tKp[t],
            wth + (size_t)t * 400 * KP_MAX, wtl + (size_t)t * 400 * KP_MAX);
    }

    zero_cnt_kernel<<<(4 * NNODES + 255) / 256, 256>>>(ecnt, 4 * NNODES);
    {
        dim3 grid((MAX_NNZ + 255) / 256, 4);
        ell_build4_kernel<<<grid, 256>>>(
            (const int*)d_in[1], (const int*)d_in[2], (const float*)d_in[3], in_sizes[1],
            (const int*)d_in[4], (const int*)d_in[5], (const float*)d_in[6], in_sizes[4],
            (const int*)d_in[7], (const int*)d_in[8], (const float*)d_in[9], in_sizes[7],
            (const int*)d_in[10], (const int*)d_in[11], (const float*)d_in[12], in_sizes[10],
            evals, ecols, ecnt);
    }

    transpose_in_kernel<<<(BATCH * NNODES + 255) / 256, 256>>>(H, sa);

    // Layer 0 (fp32): y = sa @ W0 + b0   [65280 x 400], K=2
    {
        dim3 grid((400 + 63) / 64, MROWS / 64);
        sgemm_kernel<<<grid, 256>>>(sa, (const float*)d_in[13], (const float*)d_in[14],
                                    y, MROWS, 400, 2, 2, 400, 400);
    }
    // spmm0 (sm_s): y[.,400] -> split X, kp=416
    {
        dim3 grid((BATCH * (416 / 4) + 255) / 256, NNODES);
        spmm_split_kernel<<<grid, 256>>>(evals, ecols, ecnt, y, 400, 416, xh, xl);
    }

    // Tensor layers; spmm adj: l1=sm_s(0), l2=sm_t(1), l3=sp_t(3), l4=sp_s(2)
    const int adjT[4] = {0, 1, 3, 2};
    const int nextKp[4] = {320, 128, 320, 0};
    for (int t = 0; t < 4; t++) {
        const float* bias = (const float*)d_in[tW[t] + 1];
        {
            dim3 grid((tN[t] + BN - 1) / BN, MROWS / BM);
            gemm_bf16x3_mma<<<grid, 256, SMEM_GEMM>>>(
                xh, xl,
                wth + (size_t)t * 400 * KP_MAX, wtl + (size_t)t * 400 * KP_MAX,
                bias, y, tN[t], tKp[t]);
        }
        const int a = adjT[t];
        if (t < 3) {
            dim3 grid((BATCH * (nextKp[t] / 4) + 255) / 256, NNODES);
            spmm_split_kernel<<<grid, 256>>>(evals + (size_t)a * NNODES * ELL_CAP,
                                             ecols + (size_t)a * NNODES * ELL_CAP,
                                             ecnt + a * NNODES, y, tN[t], nextKp[t], xh, xl);
        } else {
            dim3 grid((BATCH * (400 / 4) + 255) / 256, NNODES);
            spmm_f32_v4_kernel<<<grid, 256>>>(evals + (size_t)a * NNODES * ELL_CAP,
                                              ecols + (size_t)a * NNODES * ELL_CAP,
                                              ecnt + a * NNODES, y, 400, y2);
        }
    }

    // Layer 5 (fp32): sa = y2 @ Wd2 + bd2   [65280 x 2], K=400  (lda=400!)
    {
        dim3 grid(1, MROWS / 64);
        sgemm_kernel<<<grid, 256>>>(y2, (const float*)d_in[23], (const float*)d_in[24],
                                    sa, MROWS, 2, 400, 400, 2, 2);
    }
    // spmm5 (sp_s): do=2
    {
        dim3 grid(1, NNODES);
        spmm_f32_v2_kernel<<<grid, 256>>>(evals + 2 * (size_t)NNODES * ELL_CAP,
                                          ecols + 2 * (size_t)NNODES * ELL_CAP,
                                          ecnt + 2 * NNODES, sa, 2, sbuf);
    }

    transpose_out_kernel<<<(BATCH * NNODES + 255) / 256, 256>>>(sbuf, (float*)d_out);
}

// round 6
// speedup vs baseline: 3.4411x; 1.2511x over previous
#include <cuda_runtime.h>
#include <cuda_bf16.h>
#include <cstdint>

#define NNODES 255
#define BATCH  256
#define MROWS  (NNODES * BATCH)   // 65280
#define ELL_CAP 64
#define MAX_NNZ 2048
#define KP_MAX  416

// ---------------------------------------------------------------------------
// Scratch (no cudaMalloc allowed)
// ---------------------------------------------------------------------------
__device__ __align__(128) float          g_y   [MROWS * 304];        // Form-O GEMM out (max 300)
__device__ __align__(128) __nv_bfloat16  g_xh  [MROWS * KP_MAX];     // split activations hi
__device__ __align__(128) __nv_bfloat16  g_xl  [MROWS * KP_MAX];
__device__ __align__(128) __nv_bfloat16  g_uh  [MROWS * KP_MAX];     // Form-I spmm out hi
__device__ __align__(128) __nv_bfloat16  g_ul  [MROWS * KP_MAX];
__device__ __align__(128) __nv_bfloat16  g_wth [5 * 400 * KP_MAX];   // W^T hi, K-padded
__device__ __align__(128) __nv_bfloat16  g_wtl [5 * 400 * KP_MAX];
__device__ __align__(128) float          g_sa  [MROWS * 2];          // small fp32 (L0 U, L5 Y)
__device__ float g_ell_vals[4 * NNODES * ELL_CAP];
__device__ int   g_ell_cols[4 * NNODES * ELL_CAP];
__device__ int   g_ell_cnt [4 * NNODES];
__device__ float g_rowsum  [4 * NNODES];

// ---------------------------------------------------------------------------
// PTX helpers (family-neutral: mma.sync / ldmatrix / cp.async)
// ---------------------------------------------------------------------------
__device__ __forceinline__ uint32_t smem_u32(const void* p) {
    uint32_t a;
    asm("{ .reg .u64 t; cvta.to.shared.u64 t, %1; cvt.u32.u64 %0, t; }"
        : "=r"(a) : "l"(p));
    return a;
}
__device__ __forceinline__ void cp16(uint32_t dst, const void* src, uint32_t bytes) {
    asm volatile("cp.async.cg.shared.global [%0], [%1], 16, %2;"
                 :: "r"(dst), "l"(src), "r"(bytes) : "memory");
}
#define CP_COMMIT() asm volatile("cp.async.commit_group;" ::: "memory")
#define CP_WAIT(n)  asm volatile("cp.async.wait_group %0;" :: "n"(n) : "memory")

__device__ __forceinline__ void ldsm4(uint32_t* r, uint32_t addr) {
    asm volatile("ldmatrix.sync.aligned.m8n8.x4.shared.b16 {%0,%1,%2,%3}, [%4];"
                 : "=r"(r[0]), "=r"(r[1]), "=r"(r[2]), "=r"(r[3]) : "r"(addr));
}
__device__ __forceinline__ void ldsm2(uint32_t* r, uint32_t addr) {
    asm volatile("ldmatrix.sync.aligned.m8n8.x2.shared.b16 {%0,%1}, [%2];"
                 : "=r"(r[0]), "=r"(r[1]) : "r"(addr));
}
__device__ __forceinline__ void mma16816(float* c, const uint32_t* a, const uint32_t* b) {
    asm volatile("mma.sync.aligned.m16n8k16.row.col.f32.bf16.bf16.f32 "
                 "{%0,%1,%2,%3}, {%4,%5,%6,%7}, {%8,%9}, {%0,%1,%2,%3};"
                 : "+f"(c[0]), "+f"(c[1]), "+f"(c[2]), "+f"(c[3])
                 : "r"(a[0]), "r"(a[1]), "r"(a[2]), "r"(a[3]), "r"(b[0]), "r"(b[1]));
}

__device__ __forceinline__ uint32_t split_pack_hi(float v0, float v1, uint32_t& lo_bits) {
    __nv_bfloat162 h = __floats2bfloat162_rn(v0, v1);
    float2 hf = __bfloat1622float2(h);
    __nv_bfloat162 l = __floats2bfloat162_rn(v0 - hf.x, v1 - hf.y);
    lo_bits = *reinterpret_cast<uint32_t*>(&l);
    return *reinterpret_cast<uint32_t*>(&h);
}

// ---------------------------------------------------------------------------
// bf16x3 HMMA GEMM. SPLIT=false: Y[M,Nfull] = A@B^T + bias (fp32 out).
// SPLIT=true : Oh/Ol[M,Kpn] = split(relu(A@B^T + s[node]*bias)), zero pad cols.
// CTA 128x128x32, 256 thr, warp 64x32, cp.async double buffer.
// ---------------------------------------------------------------------------
#define BM 128
#define BN 128
#define BK 32
#define LDT 40
#define TILE_B (128 * LDT * 2)
#define STAGE_B (4 * TILE_B)

template <bool SPLIT>
__global__ __launch_bounds__(256)
void gemm_bf16x3_mma(const __nv_bfloat16* __restrict__ Ah,
                     const __nv_bfloat16* __restrict__ Al,
                     const __nv_bfloat16* __restrict__ Bh,
                     const __nv_bfloat16* __restrict__ Bl,
                     const float* __restrict__ bias,
                     const float* __restrict__ srow,
                     float* __restrict__ Y,
                     __nv_bfloat16* __restrict__ Oh,
                     __nv_bfloat16* __restrict__ Ol,
                     int Nfull, int Kp, int Kpn) {
    extern __shared__ __align__(128) char smem[];
    const uint32_t sb = smem_u32(smem);

    const int tid  = threadIdx.x;
    const int lane = tid & 31;
    const int wid  = tid >> 5;
    const int wm   = wid & 1;
    const int wn   = wid >> 1;
    const int m0   = blockIdx.y * BM;
    const int n0   = blockIdx.x * BN;

    const int nblk = Kp >> 5;

    auto load_stage = [&](int blk, int s) {
        const int k0 = blk << 5;
        const uint32_t sdst = sb + s * STAGE_B;
        #pragma unroll
        for (int i = 0; i < 8; i++) {
            const int idx = i * 256 + tid;
            const int mat = idx >> 9;
            const int c   = idx & 511;
            const int row = c >> 2;
            const int seg = c & 3;
            const uint32_t dst = sdst + mat * TILE_B + (row * LDT + seg * 8) * 2;
            if (mat < 2) {
                const __nv_bfloat16* src = (mat == 0 ? Ah : Al);
                cp16(dst, src + (size_t)(m0 + row) * Kp + k0 + seg * 8, 16);
            } else {
                const __nv_bfloat16* src = (mat == 2 ? Bh : Bl);
                const int gr = n0 + row;
                const int ok = gr < Nfull;
                cp16(dst, src + (size_t)(ok ? gr : 0) * Kp + k0 + seg * 8, ok ? 16 : 0);
            }
        }
        CP_COMMIT();
    };

    float acc[4][4][4];
    #pragma unroll
    for (int i = 0; i < 4; i++)
        #pragma unroll
        for (int j = 0; j < 4; j++)
            #pragma unroll
            for (int q = 0; q < 4; q++) acc[i][j][q] = 0.0f;

    load_stage(0, 0);

    for (int blk = 0; blk < nblk; blk++) {
        const int s = blk & 1;
        __syncthreads();
        if (blk + 1 < nblk) { load_stage(blk + 1, s ^ 1); CP_WAIT(1); }
        else                { CP_WAIT(0); }
        __syncthreads();

        const uint32_t stage = sb + s * STAGE_B;
        #pragma unroll
        for (int ks = 0; ks < BK; ks += 16) {
            uint32_t ah[4][4], al[4][4], bh[4][2], bl[4][2];
            const int arow = wm * 64 + (lane & 15);
            const int akoff = ks + ((lane >> 4) << 3);
            #pragma unroll
            for (int mi = 0; mi < 4; mi++) {
                const uint32_t off = ((arow + mi * 16) * LDT + akoff) * 2;
                ldsm4(ah[mi], stage + off);
                ldsm4(al[mi], stage + TILE_B + off);
            }
            const int brow = wn * 32 + (lane & 7);
            const int bkoff = ks + (((lane >> 3) & 1) << 3);
            #pragma unroll
            for (int ni = 0; ni < 4; ni++) {
                const uint32_t off = ((brow + ni * 8) * LDT + bkoff) * 2;
                ldsm2(bh[ni], stage + 2 * TILE_B + off);
                ldsm2(bl[ni], stage + 3 * TILE_B + off);
            }
            #pragma unroll
            for (int mi = 0; mi < 4; mi++)
                #pragma unroll
                for (int ni = 0; ni < 4; ni++) {
                    mma16816(acc[mi][ni], ah[mi], bh[ni]);
                    mma16816(acc[mi][ni], ah[mi], bl[ni]);
                    mma16816(acc[mi][ni], al[mi], bh[ni]);
                }
        }
    }

    if (!SPLIT) {
        #pragma unroll
        for (int ni = 0; ni < 4; ni++) {
            const int gc = n0 + wn * 32 + ni * 8 + (lane & 3) * 2;
            if (gc >= Nfull) continue;
            const float b0 = bias[gc], b1 = bias[gc + 1];
            #pragma unroll
            for (int mi = 0; mi < 4; mi++) {
                const int gr = m0 + wm * 64 + mi * 16 + (lane >> 2);
                float2 v0 = make_float2(acc[mi][ni][0] + b0, acc[mi][ni][1] + b1);
                float2 v1 = make_float2(acc[mi][ni][2] + b0, acc[mi][ni][3] + b1);
                *(float2*)(Y + (size_t)gr * Nfull + gc) = v0;
                *(float2*)(Y + (size_t)(gr + 8) * Nfull + gc) = v1;
            }
        }
    } else {
        const float s = srow[m0 >> 8];     // all 128 rows in one node block
        #pragma unroll
        for (int ni = 0; ni < 4; ni++) {
            const int gc = n0 + wn * 32 + ni * 8 + (lane & 3) * 2;
            if (gc >= Kpn) continue;
            const float b0 = (gc < Nfull) ? s * bias[gc] : 0.0f;
            const float b1 = (gc + 1 < Nfull) ? s * bias[gc + 1] : 0.0f;
            #pragma unroll
            for (int mi = 0; mi < 4; mi++) {
                const int gr = m0 + wm * 64 + mi * 16 + (lane >> 2);
                float v00 = fmaxf(acc[mi][ni][0] + b0, 0.0f);
                float v01 = fmaxf(acc[mi][ni][1] + b1, 0.0f);
                float v10 = fmaxf(acc[mi][ni][2] + b0, 0.0f);
                float v11 = fmaxf(acc[mi][ni][3] + b1, 0.0f);
                uint32_t lo0, lo1;
                uint32_t hi0 = split_pack_hi(v00, v01, lo0);
                uint32_t hi1 = split_pack_hi(v10, v11, lo1);
                *(uint32_t*)(Oh + (size_t)gr * Kpn + gc) = hi0;
                *(uint32_t*)(Ol + (size_t)gr * Kpn + gc) = lo0;
                *(uint32_t*)(Oh + (size_t)(gr + 8) * Kpn + gc) = hi1;
                *(uint32_t*)(Ol + (size_t)(gr + 8) * Kpn + gc) = lo1;
            }
        }
    }
}

// ---------------------------------------------------------------------------
// Weight prep: Wt_h/Wt_l[n, k] = split(W[k, n]), zero-padded k in [K, Kp)
// ---------------------------------------------------------------------------
__global__ void wt_split_kernel(const float* __restrict__ W, int K, int N, int Kp,
                                __nv_bfloat16* __restrict__ wh,
                                __nv_bfloat16* __restrict__ wl) {
    int i = blockIdx.x * 256 + threadIdx.x;
    if (i >= N * Kp) return;
    int n = i / Kp, k = i - n * Kp;
    float v = (k < K) ? W[(size_t)k * N + n] : 0.0f;
    __nv_bfloat16 h = __float2bfloat16(v);
    wh[i] = h;
    wl[i] = __float2bfloat16(v - __bfloat162float(h));
}

// ---------------------------------------------------------------------------
// ELL build (4 operators, one launch; deterministic slot order) + rowsums
// ---------------------------------------------------------------------------
__global__ void ell_build4_kernel(const int* r0, const int* c0, const float* v0, int n0_,
                                  const int* r1, const int* c1, const float* v1, int n1_,
                                  const int* r2, const int* c2, const float* v2, int n2_,
                                  const int* r3, const int* c3, const float* v3, int n3_,
                                  float* evals, int* ecols, int* cnt) {
    const int w = blockIdx.y;
    const int* rows = w == 0 ? r0 : w == 1 ? r1 : w == 2 ? r2 : r3;
    const int* cols = w == 0 ? c0 : w == 1 ? c1 : w == 2 ? c2 : c3;
    const float* vals = w == 0 ? v0 : w == 1 ? v1 : w == 2 ? v2 : v3;
    const int nnz = w == 0 ? n0_ : w == 1 ? n1_ : w == 2 ? n2_ : n3_;
    float* ev = evals + (size_t)w * NNODES * ELL_CAP;
    int* ec = ecols + (size_t)w * NNODES * ELL_CAP;
    int* cn = cnt + w * NNODES;

    __shared__ int srows[MAX_NNZ];
    const int tid = threadIdx.x;
    const int nld = nnz < MAX_NNZ ? nnz : MAX_NNZ;
    for (int i = tid; i < nld; i += blockDim.x) srows[i] = rows[i];
    __syncthreads();

    const int e = blockIdx.x * blockDim.x + tid;
    if (e < nnz) {
        const int r = (e < MAX_NNZ) ? srows[e] : rows[e];
        int slot = 0;
        for (int k = 0; k < e && k < MAX_NNZ; k++) slot += (srows[k] == r);
        if (slot < ELL_CAP) {
            ev[r * ELL_CAP + slot] = vals[e];
            ec[r * ELL_CAP + slot] = cols[e];
            atomicMax(&cn[r], slot + 1);
        }
    }
}

__global__ void zero_cnt_kernel(int* cnt, int n) {
    int i = blockIdx.x * 256 + threadIdx.x;
    if (i < n) cnt[i] = 0;
}

__global__ void rowsum_kernel(const float* __restrict__ evals,
                              const int* __restrict__ cnt, float* __restrict__ srow) {
    int i = blockIdx.x * 256 + threadIdx.x;
    if (i >= 4 * NNODES) return;
    const int n = cnt[i];
    float s = 0.0f;
    for (int j = 0; j < n; j++) s += evals[(size_t)i * ELL_CAP + j];
    srow[i] = s;
}

// ---------------------------------------------------------------------------
// L0 fused pair.
// spmm_in: U0[(r*256+b), 0:2] = sum_j val_j * H[b, c_j, 0:2]   (no relu)
// l0_proj: xh/xl[m, c] = split(relu(U0[m,0]*W0[0,c] + U0[m,1]*W0[1,c] + s*b0[c]))
// ---------------------------------------------------------------------------
__global__ __launch_bounds__(256)
void spmm_in_kernel(const float* __restrict__ evals, const int* __restrict__ ecols,
                    const int* __restrict__ cnt, const float* __restrict__ H,
                    float* __restrict__ U0) {
    const int r = blockIdx.x;
    const int b = threadIdx.x;
    const int n = cnt[r];
    __shared__ float sv[ELL_CAP];
    __shared__ int   sc[ELL_CAP];
    if (b < n) { sv[b] = evals[r * ELL_CAP + b]; sc[b] = ecols[r * ELL_CAP + b]; }
    __syncthreads();
    float a0 = 0.0f, a1 = 0.0f;
    for (int j = 0; j < n; j++) {
        const float v = sv[j];
        const float2 h = *(const float2*)(H + ((size_t)b * NNODES + sc[j]) * 2);
        a0 = fmaf(v, h.x, a0);
        a1 = fmaf(v, h.y, a1);
    }
    *(float2*)(U0 + ((size_t)r * BATCH + b) * 2) = make_float2(a0, a1);
}

__global__ __launch_bounds__(256)
void l0_proj_kernel(const float* __restrict__ U0, const float* __restrict__ W0,
                    const float* __restrict__ bias, const float* __restrict__ srow,
                    __nv_bfloat16* __restrict__ Oh, __nv_bfloat16* __restrict__ Ol) {
    const int NF4 = KP_MAX / 4;                    // 104
    const int p = blockIdx.x * 256 + threadIdx.x;
    if (p >= MROWS * NF4) return;
    const int m = p / NF4;
    const int f = (p - m * NF4) * 4;
    const float2 u = *(const float2*)(U0 + (size_t)m * 2);
    const float s = srow[m >> 8];
    float v[4];
    #pragma unroll
    for (int q = 0; q < 4; q++) {
        const int c = f + q;
        v[q] = (c < 400)
             ? fmaxf(fmaf(u.x, W0[c], fmaf(u.y, W0[400 + c], s * bias[c])), 0.0f)
             : 0.0f;
    }
    uint32_t lo0, lo1;
    uint32_t hi0 = split_pack_hi(v[0], v[1], lo0);
    uint32_t hi1 = split_pack_hi(v[2], v[3], lo1);
    const size_t o = (size_t)m * KP_MAX + f;
    *(uint2*)(Oh + o) = make_uint2(hi0, hi1);
    *(uint2*)(Ol + o) = make_uint2(lo0, lo1);
}

// ---------------------------------------------------------------------------
// Form-O spmm: split(relu(A @ Y)) ; Y fp32 [M, do], out split [M, Kp] (pad 0)
// ---------------------------------------------------------------------------
__global__ __launch_bounds__(256)
void spmm_relu_split_kernel(const float* __restrict__ evals, const int* __restrict__ ecols,
                            const int* __restrict__ cnt, const float* __restrict__ Y,
                            int do_, int kp,
                            __nv_bfloat16* __restrict__ xh, __nv_bfloat16* __restrict__ xl) {
    const int r = blockIdx.y;
    const int n = cnt[r];
    __shared__ float sv[ELL_CAP];
    __shared__ int   sc[ELL_CAP];
    if (threadIdx.x < n) {
        sv[threadIdx.x] = evals[r * ELL_CAP + threadIdx.x];
        sc[threadIdx.x] = ecols[r * ELL_CAP + threadIdx.x];
    }
    __syncthreads();

    const int nF4 = kp >> 2;
    const int p = blockIdx.x * 256 + threadIdx.x;
    if (p >= BATCH * nF4) return;
    const int b = p / nF4, f = (p - b * nF4) * 4;
    const size_t obase = ((size_t)r * BATCH + b) * kp + f;

    if (f >= do_) {
        *(uint2*)(xh + obase) = make_uint2(0, 0);
        *(uint2*)(xl + obase) = make_uint2(0, 0);
        return;
    }
    float4 acc = make_float4(0.f, 0.f, 0.f, 0.f);
    for (int j = 0; j < n; j++) {
        const float a = sv[j];
        const float4 x = *(const float4*)(Y + ((size_t)sc[j] * BATCH + b) * do_ + f);
        acc.x = fmaf(a, x.x, acc.x);
        acc.y = fmaf(a, x.y, acc.y);
        acc.z = fmaf(a, x.z, acc.z);
        acc.w = fmaf(a, x.w, acc.w);
    }
    acc.x = fmaxf(acc.x, 0.f); acc.y = fmaxf(acc.y, 0.f);
    acc.z = fmaxf(acc.z, 0.f); acc.w = fmaxf(acc.w, 0.f);

    uint32_t lo0, lo1;
    uint32_t hi0 = split_pack_hi(acc.x, acc.y, lo0);
    uint32_t hi1 = split_pack_hi(acc.z, acc.w, lo1);
    *(uint2*)(xh + obase) = make_uint2(hi0, hi1);
    *(uint2*)(xl + obase) = make_uint2(lo0, lo1);
}

// ---------------------------------------------------------------------------
// Form-I spmm: U = A @ X, split in / split out, NO relu. Same Kp in/out.
// Pads stay zero automatically (sum of zeros).
// ---------------------------------------------------------------------------
__global__ __launch_bounds__(256)
void spmm_ss_kernel(const float* __restrict__ evals, const int* __restrict__ ecols,
                    const int* __restrict__ cnt,
                    const __nv_bfloat16* __restrict__ xh, const __nv_bfloat16* __restrict__ xl,
                    int kp,
                    __nv_bfloat16* __restrict__ uh, __nv_bfloat16* __restrict__ ul) {
    const int r = blockIdx.y;
    const int n = cnt[r];
    __shared__ float sv[ELL_CAP];
    __shared__ int   sc[ELL_CAP];
    if (threadIdx.x < n) {
        sv[threadIdx.x] = evals[r * ELL_CAP + threadIdx.x];
        sc[threadIdx.x] = ecols[r * ELL_CAP + threadIdx.x];
    }
    __syncthreads();

    const int nF4 = kp >> 2;
    const int p = blockIdx.x * 256 + threadIdx.x;
    if (p >= BATCH * nF4) return;
    const int b = p / nF4, f = (p - b * nF4) * 4;

    float4 acc = make_float4(0.f, 0.f, 0.f, 0.f);
    for (int j = 0; j < n; j++) {
        const float a = sv[j];
        const size_t base = ((size_t)sc[j] * BATCH + b) * kp + f;
        const uint2 hh = *(const uint2*)(xh + base);
        const uint2 ll = *(const uint2*)(xl + base);
        float2 h0 = __bfloat1622float2(*reinterpret_cast<const __nv_bfloat162*>(&hh.x));
        float2 h1 = __bfloat1622float2(*reinterpret_cast<const __nv_bfloat162*>(&hh.y));
        float2 l0 = __bfloat1622float2(*reinterpret_cast<const __nv_bfloat162*>(&ll.x));
        float2 l1 = __bfloat1622float2(*reinterpret_cast<const __nv_bfloat162*>(&ll.y));
        acc.x = fmaf(a, h0.x + l0.x, acc.x);
        acc.y = fmaf(a, h0.y + l0.y, acc.y);
        acc.z = fmaf(a, h1.x + l1.x, acc.z);
        acc.w = fmaf(a, h1.y + l1.y, acc.w);
    }
    uint32_t lo0, lo1;
    uint32_t hi0 = split_pack_hi(acc.x, acc.y, lo0);
    uint32_t hi1 = split_pack_hi(acc.z, acc.w, lo1);
    const size_t obase = ((size_t)r * BATCH + b) * kp + f;
    *(uint2*)(uh + obase) = make_uint2(hi0, hi1);
    *(uint2*)(ul + obase) = make_uint2(lo0, lo1);
}

// ---------------------------------------------------------------------------
// L5 fused: out[b, r, 0:2] = relu( sum_j val_j * Y[(c_j*256+b), 0:2] )
// (spmm + relu + output transpose in one pass)
// ---------------------------------------------------------------------------
__global__ __launch_bounds__(256)
void spmm_out_kernel(const float* __restrict__ evals, const int* __restrict__ ecols,
                     const int* __restrict__ cnt, const float* __restrict__ Y,
                     float* __restrict__ out) {
    const int r = blockIdx.x;
    const int b = threadIdx.x;
    const int n = cnt[r];
    __shared__ float sv[ELL_CAP];
    __shared__ int   sc[ELL_CAP];
    if (b < n) { sv[b] = evals[r * ELL_CAP + b]; sc[b] = ecols[r * ELL_CAP + b]; }
    __syncthreads();
    float a0 = 0.0f, a1 = 0.0f;
    for (int j = 0; j < n; j++) {
        const float v = sv[j];
        const float2 y = *(const float2*)(Y + ((size_t)sc[j] * BATCH + b) * 2);
        a0 = fmaf(v, y.x, a0);
        a1 = fmaf(v, y.y, a1);
    }
    *(float2*)(out + ((size_t)b * NNODES + r) * 2) =
        make_float2(fmaxf(a0, 0.0f), fmaxf(a1, 0.0f));
}

// ---------------------------------------------------------------------------
// Launch
// Layers:          adj        form   spmm cols
//  L0 2->400      sm_s(0)     I      2   (fused input gather)
//  L1 400->300    sm_s(0)     O      300 -> Kp 320
//  L2 300->100    sm_t(1)     O      100 -> Kp 128
//  L3 100->300    sp_t(3)     I      128 (split->split)
//  L4 300->400    sp_s(2)     I      320 (split->split)
//  L5 400->2      sp_s(2)     O      2   (fused output transpose)
// ---------------------------------------------------------------------------
extern "C" void kernel_launch(void* const* d_in, const int* in_sizes, int n_in,
                              void* d_out, int out_size) {
    const float* H = (const float*)d_in[0];

    float *y, *sa, *evals, *rowsum;
    __nv_bfloat16 *xh, *xl, *uh, *ul, *wth, *wtl;
    int *ecols, *ecnt;
    cudaGetSymbolAddress((void**)&y,     g_y);
    cudaGetSymbolAddress((void**)&xh,    g_xh);
    cudaGetSymbolAddress((void**)&xl,    g_xl);
    cudaGetSymbolAddress((void**)&uh,    g_uh);
    cudaGetSymbolAddress((void**)&ul,    g_ul);
    cudaGetSymbolAddress((void**)&wth,   g_wth);
    cudaGetSymbolAddress((void**)&wtl,   g_wtl);
    cudaGetSymbolAddress((void**)&sa,    g_sa);
    cudaGetSymbolAddress((void**)&evals, g_ell_vals);
    cudaGetSymbolAddress((void**)&ecols, g_ell_cols);
    cudaGetSymbolAddress((void**)&ecnt,  g_ell_cnt);
    cudaGetSymbolAddress((void**)&rowsum, g_rowsum);

    const int SMEM_GEMM = 2 * STAGE_B;
    cudaFuncSetAttribute(gemm_bf16x3_mma<false>,
                         cudaFuncAttributeMaxDynamicSharedMemorySize, SMEM_GEMM);
    cudaFuncSetAttribute(gemm_bf16x3_mma<true>,
                         cudaFuncAttributeMaxDynamicSharedMemorySize, SMEM_GEMM);

    // HMMA weight prep: L1..L5 (W1, W2, Wd0, Wd1, Wd2), K padded to 32.
    const int tK[5]  = {400, 300, 100, 300, 400};
    const int tN[5]  = {300, 100, 300, 400, 2};
    const int tKp[5] = {416, 320, 128, 320, 416};
    const int tW[5]  = {15, 17, 19, 21, 23};
    for (int t = 0; t < 5; t++) {
        int tot = tN[t] * tKp[t];
        wt_split_kernel<<<(tot + 255) / 256, 256>>>(
            (const float*)d_in[tW[t]], tK[t], tN[t], tKp[t],
            wth + (size_t)t * 400 * KP_MAX, wtl + (size_t)t * 400 * KP_MAX);
    }

    // ELL build: 0=sm_s, 1=sm_t, 2=sp_s, 3=sp_t; then row sums.
    zero_cnt_kernel<<<(4 * NNODES + 255) / 256, 256>>>(ecnt, 4 * NNODES);
    {
        dim3 grid((MAX_NNZ + 255) / 256, 4);
        ell_build4_kernel<<<grid, 256>>>(
            (const int*)d_in[1], (const int*)d_in[2], (const float*)d_in[3], in_sizes[1],
            (const int*)d_in[4], (const int*)d_in[5], (const float*)d_in[6], in_sizes[4],
            (const int*)d_in[7], (const int*)d_in[8], (const float*)d_in[9], in_sizes[7],
            (const int*)d_in[10], (const int*)d_in[11], (const float*)d_in[12], in_sizes[10],
            evals, ecols, ecnt);
    }
    rowsum_kernel<<<(4 * NNODES + 255) / 256, 256>>>(evals, ecnt, rowsum);

    #define EV(a) (evals + (size_t)(a) * NNODES * ELL_CAP)
    #define EC(a) (ecols + (size_t)(a) * NNODES * ELL_CAP)
    #define EN(a) (ecnt + (a) * NNODES)
    #define RS(a) (rowsum + (a) * NNODES)
    #define WH(t) (wth + (size_t)(t) * 400 * KP_MAX)
    #define WL(t) (wtl + (size_t)(t) * 400 * KP_MAX)

    // --- L0 (Form I, adj sm_s): gather-spmm on H, then K=2 projection ---
    spmm_in_kernel<<<NNODES, 256>>>(EV(0), EC(0), EN(0), H, sa);
    l0_proj_kernel<<<(MROWS * (KP_MAX / 4) + 255) / 256, 256>>>(
        sa, (const float*)d_in[13], (const float*)d_in[14], RS(0), xh, xl);

    // --- L1 (Form O, adj sm_s): GEMM -> Y[.,300]; spmm+relu+split -> Kp 320 ---
    gemm_bf16x3_mma<false><<<dim3(3, 510), 256, SMEM_GEMM>>>(
        xh, xl, WH(0), WL(0), (const float*)d_in[16], nullptr, y, nullptr, nullptr,
        300, 416, 0);
    {
        dim3 grid((BATCH * (320 / 4) + 255) / 256, NNODES);
        spmm_relu_split_kernel<<<grid, 256>>>(EV(0), EC(0), EN(0), y, 300, 320, xh, xl);
    }

    // --- L2 (Form O, adj sm_t): GEMM -> Y[.,100]; spmm+relu+split -> Kp 128 ---
    gemm_bf16x3_mma<false><<<dim3(1, 510), 256, SMEM_GEMM>>>(
        xh, xl, WH(1), WL(1), (const float*)d_in[18], nullptr, y, nullptr, nullptr,
        100, 320, 0);
    {
        dim3 grid((BATCH * (128 / 4) + 255) / 256, NNODES);
        spmm_relu_split_kernel<<<grid, 256>>>(EV(1), EC(1), EN(1), y, 100, 128, xh, xl);
    }

    // --- L3 (Form I, adj sp_t): spmm split->split (128); GEMM+relu+split -> 320 ---
    {
        dim3 grid((BATCH * (128 / 4) + 255) / 256, NNODES);
        spmm_ss_kernel<<<grid, 256>>>(EV(3), EC(3), EN(3), xh, xl, 128, uh, ul);
    }
    gemm_bf16x3_mma<true><<<dim3(3, 510), 256, SMEM_GEMM>>>(
        uh, ul, WH(2), WL(2), (const float*)d_in[20], RS(3), nullptr, xh, xl,
        300, 128, 320);

    // --- L4 (Form I, adj sp_s): spmm split->split (320); GEMM+relu+split -> 416 ---
    {
        dim3 grid((BATCH * (320 / 4) + 255) / 256, NNODES);
        spmm_ss_kernel<<<grid, 256>>>(EV(2), EC(2), EN(2), xh, xl, 320, uh, ul);
    }
    gemm_bf16x3_mma<true><<<dim3(4, 510), 256, SMEM_GEMM>>>(
        uh, ul, WH(3), WL(3), (const float*)d_in[22], RS(2), nullptr, xh, xl,
        400, 320, 416);

    // --- L5 (Form O, adj sp_s): GEMM -> Y[.,2]; fused spmm+relu+transpose ---
    gemm_bf16x3_mma<false><<<dim3(1, 510), 256, SMEM_GEMM>>>(
        xh, xl, WH(4), WL(4), (const float*)d_in[24], nullptr, sa, nullptr, nullptr,
        2, 416, 0);
    spmm_out_kernel<<<NNODES, 256>>>(EV(2), EC(2), EN(2), sa, (float*)d_out);
}

// round 7
// speedup vs baseline: 3.4470x; 1.0017x over previous
#include <cuda_runtime.h>
#include <cuda_bf16.h>
#include <cstdint>

#define NNODES 255
#define BATCH  256
#define MROWS  (NNODES * BATCH)   // 65280
#define ELL_CAP 64
#define MAX_NNZ 2048
#define KP_MAX  416

// ---------------------------------------------------------------------------
// Scratch (no cudaMalloc allowed)
// ---------------------------------------------------------------------------
__device__ __align__(128) float          g_y   [MROWS * 304];        // Form-O GEMM out (max 300)
__device__ __align__(128) __nv_bfloat16  g_xh  [MROWS * KP_MAX];
__device__ __align__(128) __nv_bfloat16  g_xl  [MROWS * KP_MAX];
__device__ __align__(128) __nv_bfloat16  g_uh  [MROWS * KP_MAX];
__device__ __align__(128) __nv_bfloat16  g_ul  [MROWS * KP_MAX];
__device__ __align__(128) __nv_bfloat16  g_wth [4 * 400 * KP_MAX];
__device__ __align__(128) __nv_bfloat16  g_wtl [4 * 400 * KP_MAX];
__device__ __align__(128) float          g_sa  [MROWS * 2];          // L0 U / L5 Y
__device__ float g_ell_vals[4 * NNODES * ELL_CAP];
__device__ int   g_ell_cols[4 * NNODES * ELL_CAP];
__device__ int   g_ell_cnt [4 * NNODES];
__device__ float g_rowsum  [4 * NNODES];

// ---------------------------------------------------------------------------
// PTX helpers (family-neutral)
// ---------------------------------------------------------------------------
__device__ __forceinline__ uint32_t smem_u32(const void* p) {
    uint32_t a;
    asm("{ .reg .u64 t; cvta.to.shared.u64 t, %1; cvt.u32.u64 %0, t; }"
        : "=r"(a) : "l"(p));
    return a;
}
__device__ __forceinline__ void cp16(uint32_t dst, const void* src, uint32_t bytes) {
    asm volatile("cp.async.cg.shared.global [%0], [%1], 16, %2;"
                 :: "r"(dst), "l"(src), "r"(bytes) : "memory");
}
#define CP_COMMIT() asm volatile("cp.async.commit_group;" ::: "memory")
#define CP_WAIT(n)  asm volatile("cp.async.wait_group %0;" :: "n"(n) : "memory")

__device__ __forceinline__ void ldsm4(uint32_t* r, uint32_t addr) {
    asm volatile("ldmatrix.sync.aligned.m8n8.x4.shared.b16 {%0,%1,%2,%3}, [%4];"
                 : "=r"(r[0]), "=r"(r[1]), "=r"(r[2]), "=r"(r[3]) : "r"(addr));
}
__device__ __forceinline__ void ldsm2(uint32_t* r, uint32_t addr) {
    asm volatile("ldmatrix.sync.aligned.m8n8.x2.shared.b16 {%0,%1}, [%2];"
                 : "=r"(r[0]), "=r"(r[1]) : "r"(addr));
}
__device__ __forceinline__ void mma16816(float* c, const uint32_t* a, const uint32_t* b) {
    asm volatile("mma.sync.aligned.m16n8k16.row.col.f32.bf16.bf16.f32 "
                 "{%0,%1,%2,%3}, {%4,%5,%6,%7}, {%8,%9}, {%0,%1,%2,%3};"
                 : "+f"(c[0]), "+f"(c[1]), "+f"(c[2]), "+f"(c[3])
                 : "r"(a[0]), "r"(a[1]), "r"(a[2]), "r"(a[3]), "r"(b[0]), "r"(b[1]));
}
__device__ __forceinline__ uint32_t split_pack_hi(float v0, float v1, uint32_t& lo_bits) {
    __nv_bfloat162 h = __floats2bfloat162_rn(v0, v1);
    float2 hf = __bfloat1622float2(h);
    __nv_bfloat162 l = __floats2bfloat162_rn(v0 - hf.x, v1 - hf.y);
    lo_bits = *reinterpret_cast<uint32_t*>(&l);
    return *reinterpret_cast<uint32_t*>(&h);
}

// ---------------------------------------------------------------------------
// bf16x3 HMMA GEMM, CTA tile 256x64x32, 256 thr, warps 4(m)x2(n), warp 64x32.
// SPLIT=false: Y[M,Nfull] = A@B^T + bias (fp32).
// SPLIT=true : Oh/Ol[M,Kpn] = split(relu(A@B^T + s[node]*bias)).
// One CTA covers exactly one node block (256 rows).
// ---------------------------------------------------------------------------
#define BM 256
#define BN 64
#define LDT 40                        // bf16 elems (80 B row stride)
#define A_TILE_B (BM * LDT * 2)       // 20480
#define B_TILE_B (BN * LDT * 2)       // 5120
#define STAGE_B (2 * A_TILE_B + 2 * B_TILE_B)   // 51200

template <bool SPLIT>
__global__ __launch_bounds__(256)
void gemm_bf16x3_mma(const __nv_bfloat16* __restrict__ Ah,
                     const __nv_bfloat16* __restrict__ Al,
                     const __nv_bfloat16* __restrict__ Bh,
                     const __nv_bfloat16* __restrict__ Bl,
                     const float* __restrict__ bias,
                     const float* __restrict__ srow,
                     float* __restrict__ Y,
                     __nv_bfloat16* __restrict__ Oh,
                     __nv_bfloat16* __restrict__ Ol,
                     int Nfull, int Kp, int Kpn) {
    extern __shared__ __align__(128) char smem[];
    const uint32_t sb = smem_u32(smem);

    const int tid  = threadIdx.x;
    const int lane = tid & 31;
    const int wid  = tid >> 5;
    const int wm   = wid & 3;            // m offset 64*wm
    const int wn   = wid >> 2;           // n offset 32*wn
    const int m0   = blockIdx.y * BM;
    const int n0   = blockIdx.x * BN;

    const int nblk = Kp >> 5;

    // Per stage: A 2048 chunks (2 mats x 256 rows x 4 segs), B 512 chunks.
    auto load_stage = [&](int blk, int s) {
        const int k0 = blk << 5;
        const uint32_t sdst = sb + s * STAGE_B;
        #pragma unroll
        for (int i = 0; i < 10; i++) {
            const int idx = i * 256 + tid;          // 0..2559
            if (idx < 2048) {
                const int mat = idx >> 10;          // 0=Ah 1=Al
                const int c   = idx & 1023;
                const int row = c >> 2;
                const int seg = c & 3;
                const uint32_t dst = sdst + mat * A_TILE_B + (row * LDT + seg * 8) * 2;
                const __nv_bfloat16* src = (mat == 0 ? Ah : Al);
                cp16(dst, src + (size_t)(m0 + row) * Kp + k0 + seg * 8, 16);
            } else {
                const int j   = idx - 2048;         // 0..511
                const int mat = j >> 8;             // 0=Bh 1=Bl
                const int c   = j & 255;
                const int row = c >> 2;
                const int seg = c & 3;
                const uint32_t dst = sdst + 2 * A_TILE_B + mat * B_TILE_B +
                                     (row * LDT + seg * 8) * 2;
                const __nv_bfloat16* src = (mat == 0 ? Bh : Bl);
                const int gr = n0 + row;
                const int ok = gr < Nfull;
                cp16(dst, src + (size_t)(ok ? gr : 0) * Kp + k0 + seg * 8, ok ? 16 : 0);
            }
        }
        CP_COMMIT();
    };

    float acc[4][4][4];
    #pragma unroll
    for (int i = 0; i < 4; i++)
        #pragma unroll
        for (int j = 0; j < 4; j++)
            #pragma unroll
            for (int q = 0; q < 4; q++) acc[i][j][q] = 0.0f;

    load_stage(0, 0);

    for (int blk = 0; blk < nblk; blk++) {
        const int s = blk & 1;
        __syncthreads();
        if (blk + 1 < nblk) { load_stage(blk + 1, s ^ 1); CP_WAIT(1); }
        else                { CP_WAIT(0); }
        __syncthreads();

        const uint32_t stage = sb + s * STAGE_B;
        #pragma unroll
        for (int ks = 0; ks < 32; ks += 16) {
            uint32_t ah[4][4], al[4][4], bh[4][2], bl[4][2];
            const int arow = wm * 64 + (lane & 15);
            const int akoff = ks + ((lane >> 4) << 3);
            #pragma unroll
            for (int mi = 0; mi < 4; mi++) {
                const uint32_t off = ((arow + mi * 16) * LDT + akoff) * 2;
                ldsm4(ah[mi], stage + off);
                ldsm4(al[mi], stage + A_TILE_B + off);
            }
            const int brow = wn * 32 + (lane & 7);
            const int bkoff = ks + (((lane >> 3) & 1) << 3);
            #pragma unroll
            for (int ni = 0; ni < 4; ni++) {
                const uint32_t off = ((brow + ni * 8) * LDT + bkoff) * 2;
                ldsm2(bh[ni], stage + 2 * A_TILE_B + off);
                ldsm2(bl[ni], stage + 2 * A_TILE_B + B_TILE_B + off);
            }
            #pragma unroll
            for (int mi = 0; mi < 4; mi++)
                #pragma unroll
                for (int ni = 0; ni < 4; ni++) {
                    mma16816(acc[mi][ni], ah[mi], bh[ni]);
                    mma16816(acc[mi][ni], ah[mi], bl[ni]);
                    mma16816(acc[mi][ni], al[mi], bh[ni]);
                }
        }
    }

    if (!SPLIT) {
        #pragma unroll
        for (int ni = 0; ni < 4; ni++) {
            const int gc = n0 + wn * 32 + ni * 8 + (lane & 3) * 2;
            if (gc >= Nfull) continue;
            const float b0 = bias[gc], b1 = bias[gc + 1];
            #pragma unroll
            for (int mi = 0; mi < 4; mi++) {
                const int gr = m0 + wm * 64 + mi * 16 + (lane >> 2);
                float2 v0 = make_float2(acc[mi][ni][0] + b0, acc[mi][ni][1] + b1);
                float2 v1 = make_float2(acc[mi][ni][2] + b0, acc[mi][ni][3] + b1);
                *(float2*)(Y + (size_t)gr * Nfull + gc) = v0;
                *(float2*)(Y + (size_t)(gr + 8) * Nfull + gc) = v1;
            }
        }
    } else {
        const float s = srow[m0 >> 8];       // one node per CTA (BM=256)
        #pragma unroll
        for (int ni = 0; ni < 4; ni++) {
            const int gc = n0 + wn * 32 + ni * 8 + (lane & 3) * 2;
            if (gc >= Kpn) continue;
            const float b0 = (gc < Nfull) ? s * bias[gc] : 0.0f;
            const float b1 = (gc + 1 < Nfull) ? s * bias[gc + 1] : 0.0f;
            #pragma unroll
            for (int mi = 0; mi < 4; mi++) {
                const int gr = m0 + wm * 64 + mi * 16 + (lane >> 2);
                float v00 = fmaxf(acc[mi][ni][0] + b0, 0.0f);
                float v01 = fmaxf(acc[mi][ni][1] + b1, 0.0f);
                float v10 = fmaxf(acc[mi][ni][2] + b0, 0.0f);
                float v11 = fmaxf(acc[mi][ni][3] + b1, 0.0f);
                uint32_t lo0, lo1;
                uint32_t hi0 = split_pack_hi(v00, v01, lo0);
                uint32_t hi1 = split_pack_hi(v10, v11, lo1);
                *(uint32_t*)(Oh + (size_t)gr * Kpn + gc) = hi0;
                *(uint32_t*)(Ol + (size_t)gr * Kpn + gc) = lo0;
                *(uint32_t*)(Oh + (size_t)(gr + 8) * Kpn + gc) = hi1;
                *(uint32_t*)(Ol + (size_t)(gr + 8) * Kpn + gc) = lo1;
            }
        }
    }
}

// ---------------------------------------------------------------------------
// L5: Y[m,0:2] = (xh[m,:]+xl[m,:]) @ Wd2[400,2] + bd2  (fp32, W in SMEM)
// ---------------------------------------------------------------------------
__global__ __launch_bounds__(256)
void l5_kernel(const __nv_bfloat16* __restrict__ xh, const __nv_bfloat16* __restrict__ xl,
               const float* __restrict__ W, const float* __restrict__ bias,
               float* __restrict__ Y) {
    __shared__ float2 Ws[400];
    for (int i = threadIdx.x; i < 400; i += 256)
        Ws[i] = make_float2(W[i * 2], W[i * 2 + 1]);
    __syncthreads();

    const int m = blockIdx.x * 256 + threadIdx.x;
    const __nv_bfloat16* ph = xh + (size_t)m * KP_MAX;
    const __nv_bfloat16* pl = xl + (size_t)m * KP_MAX;
    float a0 = bias[0], a1 = bias[1];
    #pragma unroll 2
    for (int k = 0; k < 400; k += 8) {
        const uint4 hh = *(const uint4*)(ph + k);
        const uint4 ll = *(const uint4*)(pl + k);
        const uint32_t hw[4] = {hh.x, hh.y, hh.z, hh.w};
        const uint32_t lw[4] = {ll.x, ll.y, ll.z, ll.w};
        #pragma unroll
        for (int q = 0; q < 4; q++) {
            float2 h = __bfloat1622float2(*reinterpret_cast<const __nv_bfloat162*>(&hw[q]));
            float2 l = __bfloat1622float2(*reinterpret_cast<const __nv_bfloat162*>(&lw[q]));
            const float v0 = h.x + l.x, v1 = h.y + l.y;
            const float2 w0 = Ws[k + q * 2], w1 = Ws[k + q * 2 + 1];
            a0 = fmaf(v0, w0.x, a0); a1 = fmaf(v0, w0.y, a1);
            a0 = fmaf(v1, w1.x, a0); a1 = fmaf(v1, w1.y, a1);
        }
    }
    *(float2*)(Y + (size_t)m * 2) = make_float2(a0, a1);
}

// ---------------------------------------------------------------------------
// Weight prep: Wt_h/Wt_l[n, k] = split(W[k, n]), zero-padded k in [K, Kp)
// ---------------------------------------------------------------------------
__global__ void wt_split_kernel(const float* __restrict__ W, int K, int N, int Kp,
                                __nv_bfloat16* __restrict__ wh,
                                __nv_bfloat16* __restrict__ wl) {
    int i = blockIdx.x * 256 + threadIdx.x;
    if (i >= N * Kp) return;
    int n = i / Kp, k = i - n * Kp;
    float v = (k < K) ? W[(size_t)k * N + n] : 0.0f;
    __nv_bfloat16 h = __float2bfloat16(v);
    wh[i] = h;
    wl[i] = __float2bfloat16(v - __bfloat162float(h));
}

// ---------------------------------------------------------------------------
// ELL build + rowsums
// ---------------------------------------------------------------------------
__global__ void ell_build4_kernel(const int* r0, const int* c0, const float* v0, int n0_,
                                  const int* r1, const int* c1, const float* v1, int n1_,
                                  const int* r2, const int* c2, const float* v2, int n2_,
                                  const int* r3, const int* c3, const float* v3, int n3_,
                                  float* evals, int* ecols, int* cnt) {
    const int w = blockIdx.y;
    const int* rows = w == 0 ? r0 : w == 1 ? r1 : w == 2 ? r2 : r3;
    const int* cols = w == 0 ? c0 : w == 1 ? c1 : w == 2 ? c2 : c3;
    const float* vals = w == 0 ? v0 : w == 1 ? v1 : w == 2 ? v2 : v3;
    const int nnz = w == 0 ? n0_ : w == 1 ? n1_ : w == 2 ? n2_ : n3_;
    float* ev = evals + (size_t)w * NNODES * ELL_CAP;
    int* ec = ecols + (size_t)w * NNODES * ELL_CAP;
    int* cn = cnt + w * NNODES;

    __shared__ int srows[MAX_NNZ];
    const int tid = threadIdx.x;
    const int nld = nnz < MAX_NNZ ? nnz : MAX_NNZ;
    for (int i = tid; i < nld; i += blockDim.x) srows[i] = rows[i];
    __syncthreads();

    const int e = blockIdx.x * blockDim.x + tid;
    if (e < nnz) {
        const int r = (e < MAX_NNZ) ? srows[e] : rows[e];
        int slot = 0;
        for (int k = 0; k < e && k < MAX_NNZ; k++) slot += (srows[k] == r);
        if (slot < ELL_CAP) {
            ev[r * ELL_CAP + slot] = vals[e];
            ec[r * ELL_CAP + slot] = cols[e];
            atomicMax(&cn[r], slot + 1);
        }
    }
}

__global__ void zero_cnt_kernel(int* cnt, int n) {
    int i = blockIdx.x * 256 + threadIdx.x;
    if (i < n) cnt[i] = 0;
}

__global__ void rowsum_kernel(const float* __restrict__ evals,
                              const int* __restrict__ cnt, float* __restrict__ srow) {
    int i = blockIdx.x * 256 + threadIdx.x;
    if (i >= 4 * NNODES) return;
    const int n = cnt[i];
    float s = 0.0f;
    for (int j = 0; j < n; j++) s += evals[(size_t)i * ELL_CAP + j];
    srow[i] = s;
}

// ---------------------------------------------------------------------------
// L0 fused pair
// ---------------------------------------------------------------------------
__global__ __launch_bounds__(256)
void spmm_in_kernel(const float* __restrict__ evals, const int* __restrict__ ecols,
                    const int* __restrict__ cnt, const float* __restrict__ H,
                    float* __restrict__ U0) {
    const int r = blockIdx.x;
    const int b = threadIdx.x;
    const int n = cnt[r];
    __shared__ float sv[ELL_CAP];
    __shared__ int   sc[ELL_CAP];
    if (b < n) { sv[b] = evals[r * ELL_CAP + b]; sc[b] = ecols[r * ELL_CAP + b]; }
    __syncthreads();
    float a0 = 0.0f, a1 = 0.0f;
    for (int j = 0; j < n; j++) {
        const float v = sv[j];
        const float2 h = *(const float2*)(H + ((size_t)b * NNODES + sc[j]) * 2);
        a0 = fmaf(v, h.x, a0);
        a1 = fmaf(v, h.y, a1);
    }
    *(float2*)(U0 + ((size_t)r * BATCH + b) * 2) = make_float2(a0, a1);
}

__global__ __launch_bounds__(256)
void l0_proj_kernel(const float* __restrict__ U0, const float* __restrict__ W0,
                    const float* __restrict__ bias, const float* __restrict__ srow,
                    __nv_bfloat16* __restrict__ Oh, __nv_bfloat16* __restrict__ Ol) {
    const int NF4 = KP_MAX / 4;                    // 104
    const int p = blockIdx.x * 256 + threadIdx.x;
    if (p >= MROWS * NF4) return;
    const int m = p / NF4;
    const int f = (p - m * NF4) * 4;
    const float2 u = *(const float2*)(U0 + (size_t)m * 2);
    const float s = srow[m >> 8];
    float v[4];
    #pragma unroll
    for (int q = 0; q < 4; q++) {
        const int c = f + q;
        v[q] = (c < 400)
             ? fmaxf(fmaf(u.x, W0[c], fmaf(u.y, W0[400 + c], s * bias[c])), 0.0f)
             : 0.0f;
    }
    uint32_t lo0, lo1;
    uint32_t hi0 = split_pack_hi(v[0], v[1], lo0);
    uint32_t hi1 = split_pack_hi(v[2], v[3], lo1);
    const size_t o = (size_t)m * KP_MAX + f;
    *(uint2*)(Oh + o) = make_uint2(hi0, hi1);
    *(uint2*)(Ol + o) = make_uint2(lo0, lo1);
}

// ---------------------------------------------------------------------------
// Form-O spmm: split(relu(A @ Y)) ; Y fp32 [M, do], out split [M, Kp]
// ---------------------------------------------------------------------------
__global__ __launch_bounds__(256)
void spmm_relu_split_kernel(const float* __restrict__ evals, const int* __restrict__ ecols,
                            const int* __restrict__ cnt, const float* __restrict__ Y,
                            int do_, int kp,
                            __nv_bfloat16* __restrict__ xh, __nv_bfloat16* __restrict__ xl) {
    const int r = blockIdx.y;
    const int n = cnt[r];
    __shared__ float sv[ELL_CAP];
    __shared__ int   sc[ELL_CAP];
    if (threadIdx.x < n) {
        sv[threadIdx.x] = evals[r * ELL_CAP + threadIdx.x];
        sc[threadIdx.x] = ecols[r * ELL_CAP + threadIdx.x];
    }
    __syncthreads();

    const int nF4 = kp >> 2;
    const int p = blockIdx.x * 256 + threadIdx.x;
    if (p >= BATCH * nF4) return;
    const int b = p / nF4, f = (p - b * nF4) * 4;
    const size_t obase = ((size_t)r * BATCH + b) * kp + f;

    if (f >= do_) {
        *(uint2*)(xh + obase) = make_uint2(0, 0);
        *(uint2*)(xl + obase) = make_uint2(0, 0);
        return;
    }
    float4 acc = make_float4(0.f, 0.f, 0.f, 0.f);
    for (int j = 0; j < n; j++) {
        const float a = sv[j];
        const float4 x = *(const float4*)(Y + ((size_t)sc[j] * BATCH + b) * do_ + f);
        acc.x = fmaf(a, x.x, acc.x);
        acc.y = fmaf(a, x.y, acc.y);
        acc.z = fmaf(a, x.z, acc.z);
        acc.w = fmaf(a, x.w, acc.w);
    }
    acc.x = fmaxf(acc.x, 0.f); acc.y = fmaxf(acc.y, 0.f);
    acc.z = fmaxf(acc.z, 0.f); acc.w = fmaxf(acc.w, 0.f);

    uint32_t lo0, lo1;
    uint32_t hi0 = split_pack_hi(acc.x, acc.y, lo0);
    uint32_t hi1 = split_pack_hi(acc.z, acc.w, lo1);
    *(uint2*)(xh + obase) = make_uint2(hi0, hi1);
    *(uint2*)(xl + obase) = make_uint2(lo0, lo1);
}

// ---------------------------------------------------------------------------
// Form-I spmm: U = A @ X, split in / split out, NO relu
// ---------------------------------------------------------------------------
__global__ __launch_bounds__(256)
void spmm_ss_kernel(const float* __restrict__ evals, const int* __restrict__ ecols,
                    const int* __restrict__ cnt,
                    const __nv_bfloat16* __restrict__ xh, const __nv_bfloat16* __restrict__ xl,
                    int kp,
                    __nv_bfloat16* __restrict__ uh, __nv_bfloat16* __restrict__ ul) {
    const int r = blockIdx.y;
    const int n = cnt[r];
    __shared__ float sv[ELL_CAP];
    __shared__ int   sc[ELL_CAP];
    if (threadIdx.x < n) {
        sv[threadIdx.x] = evals[r * ELL_CAP + threadIdx.x];
        sc[threadIdx.x] = ecols[r * ELL_CAP + threadIdx.x];
    }
    __syncthreads();

    const int nF4 = kp >> 2;
    const int p = blockIdx.x * 256 + threadIdx.x;
    if (p >= BATCH * nF4) return;
    const int b = p / nF4, f = (p - b * nF4) * 4;

    float4 acc = make_float4(0.f, 0.f, 0.f, 0.f);
    for (int j = 0; j < n; j++) {
        const float a = sv[j];
        const size_t base = ((size_t)sc[j] * BATCH + b) * kp + f;
        const uint2 hh = *(const uint2*)(xh + base);
        const uint2 ll = *(const uint2*)(xl + base);
        float2 h0 = __bfloat1622float2(*reinterpret_cast<const __nv_bfloat162*>(&hh.x));
        float2 h1 = __bfloat1622float2(*reinterpret_cast<const __nv_bfloat162*>(&hh.y));
        float2 l0 = __bfloat1622float2(*reinterpret_cast<const __nv_bfloat162*>(&ll.x));
        float2 l1 = __bfloat1622float2(*reinterpret_cast<const __nv_bfloat162*>(&ll.y));
        acc.x = fmaf(a, h0.x + l0.x, acc.x);
        acc.y = fmaf(a, h0.y + l0.y, acc.y);
        acc.z = fmaf(a, h1.x + l1.x, acc.z);
        acc.w = fmaf(a, h1.y + l1.y, acc.w);
    }
    uint32_t lo0, lo1;
    uint32_t hi0 = split_pack_hi(acc.x, acc.y, lo0);
    uint32_t hi1 = split_pack_hi(acc.z, acc.w, lo1);
    const size_t obase = ((size_t)r * BATCH + b) * kp + f;
    *(uint2*)(uh + obase) = make_uint2(hi0, hi1);
    *(uint2*)(ul + obase) = make_uint2(lo0, lo1);
}

// ---------------------------------------------------------------------------
// L5 fused: out[b, r, 0:2] = relu( sum_j val_j * Y[(c_j*256+b), 0:2] )
// ---------------------------------------------------------------------------
__global__ __launch_bounds__(256)
void spmm_out_kernel(const float* __restrict__ evals, const int* __restrict__ ecols,
                     const int* __restrict__ cnt, const float* __restrict__ Y,
                     float* __restrict__ out) {
    const int r = blockIdx.x;
    const int b = threadIdx.x;
    const int n = cnt[r];
    __shared__ float sv[ELL_CAP];
    __shared__ int   sc[ELL_CAP];
    if (b < n) { sv[b] = evals[r * ELL_CAP + b]; sc[b] = ecols[r * ELL_CAP + b]; }
    __syncthreads();
    float a0 = 0.0f, a1 = 0.0f;
    for (int j = 0; j < n; j++) {
        const float v = sv[j];
        const float2 y = *(const float2*)(Y + ((size_t)sc[j] * BATCH + b) * 2);
        a0 = fmaf(v, y.x, a0);
        a1 = fmaf(v, y.y, a1);
    }
    *(float2*)(out + ((size_t)b * NNODES + r) * 2) =
        make_float2(fmaxf(a0, 0.0f), fmaxf(a1, 0.0f));
}

// ---------------------------------------------------------------------------
// Launch
// ---------------------------------------------------------------------------
extern "C" void kernel_launch(void* const* d_in, const int* in_sizes, int n_in,
                              void* d_out, int out_size) {
    const float* H = (const float*)d_in[0];

    float *y, *sa, *evals, *rowsum;
    __nv_bfloat16 *xh, *xl, *uh, *ul, *wth, *wtl;
    int *ecols, *ecnt;
    cudaGetSymbolAddress((void**)&y,     g_y);
    cudaGetSymbolAddress((void**)&xh,    g_xh);
    cudaGetSymbolAddress((void**)&xl,    g_xl);
    cudaGetSymbolAddress((void**)&uh,    g_uh);
    cudaGetSymbolAddress((void**)&ul,    g_ul);
    cudaGetSymbolAddress((void**)&wth,   g_wth);
    cudaGetSymbolAddress((void**)&wtl,   g_wtl);
    cudaGetSymbolAddress((void**)&sa,    g_sa);
    cudaGetSymbolAddress((void**)&evals, g_ell_vals);
    cudaGetSymbolAddress((void**)&ecols, g_ell_cols);
    cudaGetSymbolAddress((void**)&ecnt,  g_ell_cnt);
    cudaGetSymbolAddress((void**)&rowsum, g_rowsum);

    const int SMEM_GEMM = 2 * STAGE_B;   // 102400
    cudaFuncSetAttribute(gemm_bf16x3_mma<false>,
                         cudaFuncAttributeMaxDynamicSharedMemorySize, SMEM_GEMM);
    cudaFuncSetAttribute(gemm_bf16x3_mma<true>,
                         cudaFuncAttributeMaxDynamicSharedMemorySize, SMEM_GEMM);

    // HMMA weight prep: L1..L4 (W1, W2, Wd0, Wd1), K padded to 32.
    const int tK[4]  = {400, 300, 100, 300};
    const int tN[4]  = {300, 100, 300, 400};
    const int tKp[4] = {416, 320, 128, 320};
    const int tW[4]  = {15, 17, 19, 21};
    for (int t = 0; t < 4; t++) {
        int tot = tN[t] * tKp[t];
        wt_split_kernel<<<(tot + 255) / 256, 256>>>(
            (const float*)d_in[tW[t]], tK[t], tN[t], tKp[t],
            wth + (size_t)t * 400 * KP_MAX, wtl + (size_t)t * 400 * KP_MAX);
    }

    zero_cnt_kernel<<<(4 * NNODES + 255) / 256, 256>>>(ecnt, 4 * NNODES);
    {
        dim3 grid((MAX_NNZ + 255) / 256, 4);
        ell_build4_kernel<<<grid, 256>>>(
            (const int*)d_in[1], (const int*)d_in[2], (const float*)d_in[3], in_sizes[1],
            (const int*)d_in[4], (const int*)d_in[5], (const float*)d_in[6], in_sizes[4],
            (const int*)d_in[7], (const int*)d_in[8], (const float*)d_in[9], in_sizes[7],
            (const int*)d_in[10], (const int*)d_in[11], (const float*)d_in[12], in_sizes[10],
            evals, ecols, ecnt);
    }
    rowsum_kernel<<<(4 * NNODES + 255) / 256, 256>>>(evals, ecnt, rowsum);

    #define EV(a) (evals + (size_t)(a) * NNODES * ELL_CAP)
    #define EC(a) (ecols + (size_t)(a) * NNODES * ELL_CAP)
    #define EN(a) (ecnt + (a) * NNODES)
    #define RS(a) (rowsum + (a) * NNODES)
    #define WH(t) (wth + (size_t)(t) * 400 * KP_MAX)
    #define WL(t) (wtl + (size_t)(t) * 400 * KP_MAX)

    // --- L0 (Form I, sm_s): gather-spmm on H, then K=2 projection ---
    spmm_in_kernel<<<NNODES, 256>>>(EV(0), EC(0), EN(0), H, sa);
    l0_proj_kernel<<<(MROWS * (KP_MAX / 4) + 255) / 256, 256>>>(
        sa, (const float*)d_in[13], (const float*)d_in[14], RS(0), xh, xl);

    // --- L1 (Form O, sm_s): GEMM -> Y[.,300]; spmm+relu+split -> Kp 320 ---
    gemm_bf16x3_mma<false><<<dim3(5, NNODES), 256, SMEM_GEMM>>>(
        xh, xl, WH(0), WL(0), (const float*)d_in[16], nullptr, y, nullptr, nullptr,
        300, 416, 0);
    {
        dim3 grid((BATCH * (320 / 4) + 255) / 256, NNODES);
        spmm_relu_split_kernel<<<grid, 256>>>(EV(0), EC(0), EN(0), y, 300, 320, xh, xl);
    }

    // --- L2 (Form O, sm_t): GEMM -> Y[.,100]; spmm+relu+split -> Kp 128 ---
    gemm_bf16x3_mma<false><<<dim3(2, NNODES), 256, SMEM_GEMM>>>(
        xh, xl, WH(1), WL(1), (const float*)d_in[18], nullptr, y, nullptr, nullptr,
        100, 320, 0);
    {
        dim3 grid((BATCH * (128 / 4) + 255) / 256, NNODES);
        spmm_relu_split_kernel<<<grid, 256>>>(EV(1), EC(1), EN(1), y, 100, 128, xh, xl);
    }

    // --- L3 (Form I, sp_t): spmm split->split (128); GEMM+relu+split -> 320 ---
    {
        dim3 grid((BATCH * (128 / 4) + 255) / 256, NNODES);
        spmm_ss_kernel<<<grid, 256>>>(EV(3), EC(3), EN(3), xh, xl, 128, uh, ul);
    }
    gemm_bf16x3_mma<true><<<dim3(5, NNODES), 256, SMEM_GEMM>>>(
        uh, ul, WH(2), WL(2), (const float*)d_in[20], RS(3), nullptr, xh, xl,
        300, 128, 320);

    // --- L4 (Form I, sp_s): spmm split->split (320); GEMM+relu+split -> 416 ---
    {
        dim3 grid((BATCH * (320 / 4) + 255) / 256, NNODES);
        spmm_ss_kernel<<<grid, 256>>>(EV(2), EC(2), EN(2), xh, xl, 320, uh, ul);
    }
    gemm_bf16x3_mma<true><<<dim3(7, NNODES), 256, SMEM_GEMM>>>(
        uh, ul, WH(3), WL(3), (const float*)d_in[22], RS(2), nullptr, xh, xl,
        400, 320, 416);

    // --- L5 (Form O, sp_s): fp32 narrow GEMM -> Y[.,2]; fused spmm+transpose ---
    l5_kernel<<<NNODES, 256>>>(xh, xl, (const float*)d_in[23], (const float*)d_in[24], sa);
    spmm_out_kernel<<<NNODES, 256>>>(EV(2), EC(2), EN(2), sa, (float*)d_out);
}

// round 8
// speedup vs baseline: 3.6362x; 1.0549x over previous
#include <cuda_runtime.h>
#include <cuda_bf16.h>
#include <cstdint>

#define NNODES 255
#define BATCH  256
#define MROWS  (NNODES * BATCH)   // 65280
#define ELL_CAP 64
#define MAX_NNZ 2048
#define KP_MAX  416

// ---------------------------------------------------------------------------
// Scratch (no cudaMalloc allowed)
// ---------------------------------------------------------------------------
__device__ __align__(128) float          g_y   [MROWS * 304];
__device__ __align__(128) __nv_bfloat16  g_xh  [MROWS * KP_MAX];
__device__ __align__(128) __nv_bfloat16  g_xl  [MROWS * KP_MAX];
__device__ __align__(128) __nv_bfloat16  g_uh  [MROWS * KP_MAX];
__device__ __align__(128) __nv_bfloat16  g_ul  [MROWS * KP_MAX];
__device__ __align__(128) __nv_bfloat16  g_wth [4 * 400 * KP_MAX];
__device__ __align__(128) __nv_bfloat16  g_wtl [4 * 400 * KP_MAX];
__device__ __align__(128) float          g_sa  [MROWS * 2];
__device__ float g_ell_vals[4 * NNODES * ELL_CAP];
__device__ int   g_ell_cols[4 * NNODES * ELL_CAP];
__device__ int   g_ell_cnt [4 * NNODES];
__device__ float g_rowsum  [4 * NNODES];

// ---------------------------------------------------------------------------
// PTX helpers (family-neutral)
// ---------------------------------------------------------------------------
__device__ __forceinline__ uint32_t smem_u32(const void* p) {
    uint32_t a;
    asm("{ .reg .u64 t; cvta.to.shared.u64 t, %1; cvt.u32.u64 %0, t; }"
        : "=r"(a) : "l"(p));
    return a;
}
__device__ __forceinline__ void cp16(uint32_t dst, const void* src, uint32_t bytes) {
    asm volatile("cp.async.cg.shared.global [%0], [%1], 16, %2;"
                 :: "r"(dst), "l"(src), "r"(bytes) : "memory");
}
#define CP_COMMIT() asm volatile("cp.async.commit_group;" ::: "memory")
#define CP_WAIT(n)  asm volatile("cp.async.wait_group %0;" :: "n"(n) : "memory")

__device__ __forceinline__ void ldsm4(uint32_t* r, uint32_t addr) {
    asm volatile("ldmatrix.sync.aligned.m8n8.x4.shared.b16 {%0,%1,%2,%3}, [%4];"
                 : "=r"(r[0]), "=r"(r[1]), "=r"(r[2]), "=r"(r[3]) : "r"(addr));
}
__device__ __forceinline__ void ldsm2(uint32_t* r, uint32_t addr) {
    asm volatile("ldmatrix.sync.aligned.m8n8.x2.shared.b16 {%0,%1}, [%2];"
                 : "=r"(r[0]), "=r"(r[1]) : "r"(addr));
}
__device__ __forceinline__ void mma16816(float* c, const uint32_t* a, const uint32_t* b) {
    asm volatile("mma.sync.aligned.m16n8k16.row.col.f32.bf16.bf16.f32 "
                 "{%0,%1,%2,%3}, {%4,%5,%6,%7}, {%8,%9}, {%0,%1,%2,%3};"
                 : "+f"(c[0]), "+f"(c[1]), "+f"(c[2]), "+f"(c[3])
                 : "r"(a[0]), "r"(a[1]), "r"(a[2]), "r"(a[3]), "r"(b[0]), "r"(b[1]));
}
__device__ __forceinline__ uint32_t split_pack_hi(float v0, float v1, uint32_t& lo_bits) {
    __nv_bfloat162 h = __floats2bfloat162_rn(v0, v1);
    float2 hf = __bfloat1622float2(h);
    __nv_bfloat162 l = __floats2bfloat162_rn(v0 - hf.x, v1 - hf.y);
    lo_bits = *reinterpret_cast<uint32_t*>(&l);
    return *reinterpret_cast<uint32_t*>(&h);
}

// ---------------------------------------------------------------------------
// bf16x3 HMMA GEMM: CTA 128x128x32, 512 thr / 16 warps (4m x 4n), warp 32x32,
// 4-stage cp.async pipeline, one __syncthreads per k-block.
// SPLIT=false: Y[M,Nfull] = A@B^T + bias (fp32).
// SPLIT=true : Oh/Ol[M,Kpn] = split(relu(A@B^T + s[node]*bias)).
// ---------------------------------------------------------------------------
#define BM 128
#define BN 128
#define LDT 40                         // bf16 elems per SMEM row (80 B)
#define MAT_B (128 * LDT * 2)          // 10240 bytes per matrix tile
#define STAGE_B (4 * MAT_B)            // 40960 (Ah, Al, Bh, Bl)
#define NSTAGE 4

template <bool SPLIT>
__global__ __launch_bounds__(512, 1)
void gemm_bf16x3_mma(const __nv_bfloat16* __restrict__ Ah,
                     const __nv_bfloat16* __restrict__ Al,
                     const __nv_bfloat16* __restrict__ Bh,
                     const __nv_bfloat16* __restrict__ Bl,
                     const float* __restrict__ bias,
                     const float* __restrict__ srow,
                     float* __restrict__ Y,
                     __nv_bfloat16* __restrict__ Oh,
                     __nv_bfloat16* __restrict__ Ol,
                     int Nfull, int Kp, int Kpn) {
    extern __shared__ __align__(128) char smem[];
    const uint32_t sb = smem_u32(smem);

    const int tid  = threadIdx.x;
    const int lane = tid & 31;
    const int wid  = tid >> 5;
    const int wm   = wid & 3;            // m offset 32*wm
    const int wn   = wid >> 2;           // n offset 32*wn
    const int m0   = blockIdx.y * BM;
    const int n0   = blockIdx.x * BN;

    const int nblk = Kp >> 5;

    // 2048 chunks of 16B per stage: 4 mats x 128 rows x 4 segs; 4 per thread.
    auto load_stage = [&](int blk, int slot) {
        const int k0 = blk << 5;
        const uint32_t sdst = sb + slot * STAGE_B;
        #pragma unroll
        for (int i = 0; i < 4; i++) {
            const int idx = i * 512 + tid;          // 0..2047
            const int mat = idx >> 9;               // 0=Ah 1=Al 2=Bh 3=Bl
            const int c   = idx & 511;
            const int row = c >> 2;
            const int seg = c & 3;
            const uint32_t dst = sdst + mat * MAT_B + (row * LDT + seg * 8) * 2;
            if (mat < 2) {
                const __nv_bfloat16* src = (mat == 0 ? Ah : Al);
                cp16(dst, src + (size_t)(m0 + row) * Kp + k0 + seg * 8, 16);
            } else {
                const __nv_bfloat16* src = (mat == 2 ? Bh : Bl);
                const int gr = n0 + row;
                const int ok = gr < Nfull;
                cp16(dst, src + (size_t)(ok ? gr : 0) * Kp + k0 + seg * 8, ok ? 16 : 0);
            }
        }
        CP_COMMIT();
    };

    float acc[2][4][4];
    #pragma unroll
    for (int i = 0; i < 2; i++)
        #pragma unroll
        for (int j = 0; j < 4; j++)
            #pragma unroll
            for (int q = 0; q < 4; q++) acc[i][j][q] = 0.0f;

    // Prologue: fill 3 stages.
    #pragma unroll
    for (int s = 0; s < NSTAGE - 1; s++)
        if (s < nblk) load_stage(s, s);

    for (int blk = 0; blk < nblk; blk++) {
        const int slot = blk & (NSTAGE - 1);
        const int rem = nblk - 1 - blk;          // groups committed after blk
        if (rem >= 2)      CP_WAIT(2);
        else if (rem == 1) CP_WAIT(1);
        else               CP_WAIT(0);
        __syncthreads();

        const uint32_t stage = sb + slot * STAGE_B;
        #pragma unroll
        for (int ks = 0; ks < 32; ks += 16) {
            uint32_t ah[2][4], al[2][4], bh[4][2], bl[4][2];
            const int arow = wm * 32 + (lane & 15);
            const int akoff = ks + ((lane >> 4) << 3);
            #pragma unroll
            for (int mi = 0; mi < 2; mi++) {
                const uint32_t off = ((arow + mi * 16) * LDT + akoff) * 2;
                ldsm4(ah[mi], stage + off);
                ldsm4(al[mi], stage + MAT_B + off);
            }
            const int brow = wn * 32 + (lane & 7);
            const int bkoff = ks + (((lane >> 3) & 1) << 3);
            #pragma unroll
            for (int ni = 0; ni < 4; ni++) {
                const uint32_t off = ((brow + ni * 8) * LDT + bkoff) * 2;
                ldsm2(bh[ni], stage + 2 * MAT_B + off);
                ldsm2(bl[ni], stage + 3 * MAT_B + off);
            }
            #pragma unroll
            for (int mi = 0; mi < 2; mi++)
                #pragma unroll
                for (int ni = 0; ni < 4; ni++) {
                    mma16816(acc[mi][ni], ah[mi], bh[ni]);
                    mma16816(acc[mi][ni], ah[mi], bl[ni]);
                    mma16816(acc[mi][ni], al[mi], bh[ni]);
                }
        }

        const int nx = blk + NSTAGE - 1;
        if (nx < nblk) load_stage(nx, nx & (NSTAGE - 1));
    }

    if (!SPLIT) {
        #pragma unroll
        for (int ni = 0; ni < 4; ni++) {
            const int gc = n0 + wn * 32 + ni * 8 + (lane & 3) * 2;
            if (gc >= Nfull) continue;
            const float b0 = bias[gc], b1 = bias[gc + 1];
            #pragma unroll
            for (int mi = 0; mi < 2; mi++) {
                const int gr = m0 + wm * 32 + mi * 16 + (lane >> 2);
                float2 v0 = make_float2(acc[mi][ni][0] + b0, acc[mi][ni][1] + b1);
                float2 v1 = make_float2(acc[mi][ni][2] + b0, acc[mi][ni][3] + b1);
                *(float2*)(Y + (size_t)gr * Nfull + gc) = v0;
                *(float2*)(Y + (size_t)(gr + 8) * Nfull + gc) = v1;
            }
        }
    } else {
        const float s = srow[m0 >> 8];
        #pragma unroll
        for (int ni = 0; ni < 4; ni++) {
            const int gc = n0 + wn * 32 + ni * 8 + (lane & 3) * 2;
            if (gc >= Kpn) continue;
            const float b0 = (gc < Nfull) ? s * bias[gc] : 0.0f;
            const float b1 = (gc + 1 < Nfull) ? s * bias[gc + 1] : 0.0f;
            #pragma unroll
            for (int mi = 0; mi < 2; mi++) {
                const int gr = m0 + wm * 32 + mi * 16 + (lane >> 2);
                float v00 = fmaxf(acc[mi][ni][0] + b0, 0.0f);
                float v01 = fmaxf(acc[mi][ni][1] + b1, 0.0f);
                float v10 = fmaxf(acc[mi][ni][2] + b0, 0.0f);
                float v11 = fmaxf(acc[mi][ni][3] + b1, 0.0f);
                uint32_t lo0, lo1;
                uint32_t hi0 = split_pack_hi(v00, v01, lo0);
                uint32_t hi1 = split_pack_hi(v10, v11, lo1);
                *(uint32_t*)(Oh + (size_t)gr * Kpn + gc) = hi0;
                *(uint32_t*)(Ol + (size_t)gr * Kpn + gc) = lo0;
                *(uint32_t*)(Oh + (size_t)(gr + 8) * Kpn + gc) = hi1;
                *(uint32_t*)(Ol + (size_t)(gr + 8) * Kpn + gc) = lo1;
            }
        }
    }
}

// ---------------------------------------------------------------------------
// L5: Y[m,0:2] = (xh[m,:]+xl[m,:]) @ Wd2[400,2] + bd2
// ---------------------------------------------------------------------------
__global__ __launch_bounds__(256)
void l5_kernel(const __nv_bfloat16* __restrict__ xh, const __nv_bfloat16* __restrict__ xl,
               const float* __restrict__ W, const float* __restrict__ bias,
               float* __restrict__ Y) {
    __shared__ float2 Ws[400];
    for (int i = threadIdx.x; i < 400; i += 256)
        Ws[i] = make_float2(W[i * 2], W[i * 2 + 1]);
    __syncthreads();

    const int m = blockIdx.x * 256 + threadIdx.x;
    const __nv_bfloat16* ph = xh + (size_t)m * KP_MAX;
    const __nv_bfloat16* pl = xl + (size_t)m * KP_MAX;
    float a0 = bias[0], a1 = bias[1];
    #pragma unroll 2
    for (int k = 0; k < 400; k += 8) {
        const uint4 hh = *(const uint4*)(ph + k);
        const uint4 ll = *(const uint4*)(pl + k);
        const uint32_t hw[4] = {hh.x, hh.y, hh.z, hh.w};
        const uint32_t lw[4] = {ll.x, ll.y, ll.z, ll.w};
        #pragma unroll
        for (int q = 0; q < 4; q++) {
            float2 h = __bfloat1622float2(*reinterpret_cast<const __nv_bfloat162*>(&hw[q]));
            float2 l = __bfloat1622float2(*reinterpret_cast<const __nv_bfloat162*>(&lw[q]));
            const float v0 = h.x + l.x, v1 = h.y + l.y;
            const float2 w0 = Ws[k + q * 2], w1 = Ws[k + q * 2 + 1];
            a0 = fmaf(v0, w0.x, a0); a1 = fmaf(v0, w0.y, a1);
            a0 = fmaf(v1, w1.x, a0); a1 = fmaf(v1, w1.y, a1);
        }
    }
    *(float2*)(Y + (size_t)m * 2) = make_float2(a0, a1);
}

// ---------------------------------------------------------------------------
// Weight prep (all 4 weights, one launch): Wt[n,k] = split(W[k,n]), K zero-pad
// ---------------------------------------------------------------------------
__global__ void wt_split4_kernel(const float* W0_, const float* W1_,
                                 const float* W2_, const float* W3_,
                                 __nv_bfloat16* __restrict__ wh,
                                 __nv_bfloat16* __restrict__ wl) {
    const int t = blockIdx.y;
    const int tK[4]  = {400, 300, 100, 300};
    const int tN[4]  = {300, 100, 300, 400};
    const int tKp[4] = {416, 320, 128, 320};
    const float* W = t == 0 ? W0_ : t == 1 ? W1_ : t == 2 ? W2_ : W3_;
    const int K = tK[t], N = tN[t], Kp = tKp[t];
    int i = blockIdx.x * 256 + threadIdx.x;
    if (i >= N * Kp) return;
    int n = i / Kp, k = i - n * Kp;
    float v = (k < K) ? W[(size_t)k * N + n] : 0.0f;
    __nv_bfloat16 h = __float2bfloat16(v);
    const size_t off = (size_t)t * 400 * KP_MAX + i;
    wh[off] = h;
    wl[off] = __float2bfloat16(v - __bfloat162float(h));
}

// ---------------------------------------------------------------------------
// ELL build + rowsums
// ---------------------------------------------------------------------------
__global__ void ell_build4_kernel(const int* r0, const int* c0, const float* v0, int n0_,
                                  const int* r1, const int* c1, const float* v1, int n1_,
                                  const int* r2, const int* c2, const float* v2, int n2_,
                                  const int* r3, const int* c3, const float* v3, int n3_,
                                  float* evals, int* ecols, int* cnt) {
    const int w = blockIdx.y;
    const int* rows = w == 0 ? r0 : w == 1 ? r1 : w == 2 ? r2 : r3;
    const int* cols = w == 0 ? c0 : w == 1 ? c1 : w == 2 ? c2 : c3;
    const float* vals = w == 0 ? v0 : w == 1 ? v1 : w == 2 ? v2 : v3;
    const int nnz = w == 0 ? n0_ : w == 1 ? n1_ : w == 2 ? n2_ : n3_;
    float* ev = evals + (size_t)w * NNODES * ELL_CAP;
    int* ec = ecols + (size_t)w * NNODES * ELL_CAP;
    int* cn = cnt + w * NNODES;

    __shared__ int srows[MAX_NNZ];
    const int tid = threadIdx.x;
    const int nld = nnz < MAX_NNZ ? nnz : MAX_NNZ;
    for (int i = tid; i < nld; i += blockDim.x) srows[i] = rows[i];
    __syncthreads();

    const int e = blockIdx.x * blockDim.x + tid;
    if (e < nnz) {
        const int r = (e < MAX_NNZ) ? srows[e] : rows[e];
        int slot = 0;
        for (int k = 0; k < e && k < MAX_NNZ; k++) slot += (srows[k] == r);
        if (slot < ELL_CAP) {
            ev[r * ELL_CAP + slot] = vals[e];
            ec[r * ELL_CAP + slot] = cols[e];
            atomicMax(&cn[r], slot + 1);
        }
    }
}

__global__ void zero_cnt_kernel(int* cnt, int n) {
    int i = blockIdx.x * 256 + threadIdx.x;
    if (i < n) cnt[i] = 0;
}

__global__ void rowsum_kernel(const float* __restrict__ evals,
                              const int* __restrict__ cnt, float* __restrict__ srow) {
    int i = blockIdx.x * 256 + threadIdx.x;
    if (i >= 4 * NNODES) return;
    const int n = cnt[i];
    float s = 0.0f;
    for (int j = 0; j < n; j++) s += evals[(size_t)i * ELL_CAP + j];
    srow[i] = s;
}

// ---------------------------------------------------------------------------
// L0 fused pair
// ---------------------------------------------------------------------------
__global__ __launch_bounds__(256)
void spmm_in_kernel(const float* __restrict__ evals, const int* __restrict__ ecols,
                    const int* __restrict__ cnt, const float* __restrict__ H,
                    float* __restrict__ U0) {
    const int r = blockIdx.x;
    const int b = threadIdx.x;
    const int n = cnt[r];
    __shared__ float sv[ELL_CAP];
    __shared__ int   sc[ELL_CAP];
    if (b < n) { sv[b] = evals[r * ELL_CAP + b]; sc[b] = ecols[r * ELL_CAP + b]; }
    __syncthreads();
    float a0 = 0.0f, a1 = 0.0f;
    for (int j = 0; j < n; j++) {
        const float v = sv[j];
        const float2 h = *(const float2*)(H + ((size_t)b * NNODES + sc[j]) * 2);
        a0 = fmaf(v, h.x, a0);
        a1 = fmaf(v, h.y, a1);
    }
    *(float2*)(U0 + ((size_t)r * BATCH + b) * 2) = make_float2(a0, a1);
}

__global__ __launch_bounds__(256)
void l0_proj_kernel(const float* __restrict__ U0, const float* __restrict__ W0,
                    const float* __restrict__ bias, const float* __restrict__ srow,
                    __nv_bfloat16* __restrict__ Oh, __nv_bfloat16* __restrict__ Ol) {
    const int NF4 = KP_MAX / 4;
    const int p = blockIdx.x * 256 + threadIdx.x;
    if (p >= MROWS * NF4) return;
    const int m = p / NF4;
    const int f = (p - m * NF4) * 4;
    const float2 u = *(const float2*)(U0 + (size_t)m * 2);
    const float s = srow[m >> 8];
    float v[4];
    #pragma unroll
    for (int q = 0; q < 4; q++) {
        const int c = f + q;
        v[q] = (c < 400)
             ? fmaxf(fmaf(u.x, W0[c], fmaf(u.y, W0[400 + c], s * bias[c])), 0.0f)
             : 0.0f;
    }
    uint32_t lo0, lo1;
    uint32_t hi0 = split_pack_hi(v[0], v[1], lo0);
    uint32_t hi1 = split_pack_hi(v[2], v[3], lo1);
    const size_t o = (size_t)m * KP_MAX + f;
    *(uint2*)(Oh + o) = make_uint2(hi0, hi1);
    *(uint2*)(Ol + o) = make_uint2(lo0, lo1);
}

// ---------------------------------------------------------------------------
// Form-O spmm: split(relu(A @ Y))
// ---------------------------------------------------------------------------
__global__ __launch_bounds__(256)
void spmm_relu_split_kernel(const float* __restrict__ evals, const int* __restrict__ ecols,
                            const int* __restrict__ cnt, const float* __restrict__ Y,
                            int do_, int kp,
                            __nv_bfloat16* __restrict__ xh, __nv_bfloat16* __restrict__ xl) {
    const int r = blockIdx.y;
    const int n = cnt[r];
    __shared__ float sv[ELL_CAP];
    __shared__ int   sc[ELL_CAP];
    if (threadIdx.x < n) {
        sv[threadIdx.x] = evals[r * ELL_CAP + threadIdx.x];
        sc[threadIdx.x] = ecols[r * ELL_CAP + threadIdx.x];
    }
    __syncthreads();

    const int nF4 = kp >> 2;
    const int p = blockIdx.x * 256 + threadIdx.x;
    if (p >= BATCH * nF4) return;
    const int b = p / nF4, f = (p - b * nF4) * 4;
    const size_t obase = ((size_t)r * BATCH + b) * kp + f;

    if (f >= do_) {
        *(uint2*)(xh + obase) = make_uint2(0, 0);
        *(uint2*)(xl + obase) = make_uint2(0, 0);
        return;
    }
    float4 acc = make_float4(0.f, 0.f, 0.f, 0.f);
    for (int j = 0; j < n; j++) {
        const float a = sv[j];
        const float4 x = *(const float4*)(Y + ((size_t)sc[j] * BATCH + b) * do_ + f);
        acc.x = fmaf(a, x.x, acc.x);
        acc.y = fmaf(a, x.y, acc.y);
        acc.z = fmaf(a, x.z, acc.z);
        acc.w = fmaf(a, x.w, acc.w);
    }
    acc.x = fmaxf(acc.x, 0.f); acc.y = fmaxf(acc.y, 0.f);
    acc.z = fmaxf(acc.z, 0.f); acc.w = fmaxf(acc.w, 0.f);

    uint32_t lo0, lo1;
    uint32_t hi0 = split_pack_hi(acc.x, acc.y, lo0);
    uint32_t hi1 = split_pack_hi(acc.z, acc.w, lo1);
    *(uint2*)(xh + obase) = make_uint2(hi0, hi1);
    *(uint2*)(xl + obase) = make_uint2(lo0, lo1);
}

// ---------------------------------------------------------------------------
// Form-I spmm: U = A @ X (split->split, no relu)
// ---------------------------------------------------------------------------
__global__ __launch_bounds__(256)
void spmm_ss_kernel(const float* __restrict__ evals, const int* __restrict__ ecols,
                    const int* __restrict__ cnt,
                    const __nv_bfloat16* __restrict__ xh, const __nv_bfloat16* __restrict__ xl,
                    int kp,
                    __nv_bfloat16* __restrict__ uh, __nv_bfloat16* __restrict__ ul) {
    const int r = blockIdx.y;
    const int n = cnt[r];
    __shared__ float sv[ELL_CAP];
    __shared__ int   sc[ELL_CAP];
    if (threadIdx.x < n) {
        sv[threadIdx.x] = evals[r * ELL_CAP + threadIdx.x];
        sc[threadIdx.x] = ecols[r * ELL_CAP + threadIdx.x];
    }
    __syncthreads();

    const int nF4 = kp >> 2;
    const int p = blockIdx.x * 256 + threadIdx.x;
    if (p >= BATCH * nF4) return;
    const int b = p / nF4, f = (p - b * nF4) * 4;

    float4 acc = make_float4(0.f, 0.f, 0.f, 0.f);
    for (int j = 0; j < n; j++) {
        const float a = sv[j];
        const size_t base = ((size_t)sc[j] * BATCH + b) * kp + f;
        const uint2 hh = *(const uint2*)(xh + base);
        const uint2 ll = *(const uint2*)(xl + base);
        float2 h0 = __bfloat1622float2(*reinterpret_cast<const __nv_bfloat162*>(&hh.x));
        float2 h1 = __bfloat1622float2(*reinterpret_cast<const __nv_bfloat162*>(&hh.y));
        float2 l0 = __bfloat1622float2(*reinterpret_cast<const __nv_bfloat162*>(&ll.x));
        float2 l1 = __bfloat1622float2(*reinterpret_cast<const __nv_bfloat162*>(&ll.y));
        acc.x = fmaf(a, h0.x + l0.x, acc.x);
        acc.y = fmaf(a, h0.y + l0.y, acc.y);
        acc.z = fmaf(a, h1.x + l1.x, acc.z);
        acc.w = fmaf(a, h1.y + l1.y, acc.w);
    }
    uint32_t lo0, lo1;
    uint32_t hi0 = split_pack_hi(acc.x, acc.y, lo0);
    uint32_t hi1 = split_pack_hi(acc.z, acc.w, lo1);
    const size_t obase = ((size_t)r * BATCH + b) * kp + f;
    *(uint2*)(uh + obase) = make_uint2(hi0, hi1);
    *(uint2*)(ul + obase) = make_uint2(lo0, lo1);
}

// ---------------------------------------------------------------------------
// L5 fused spmm + relu + transpose
// ---------------------------------------------------------------------------
__global__ __launch_bounds__(256)
void spmm_out_kernel(const float* __restrict__ evals, const int* __restrict__ ecols,
                     const int* __restrict__ cnt, const float* __restrict__ Y,
                     float* __restrict__ out) {
    const int r = blockIdx.x;
    const int b = threadIdx.x;
    const int n = cnt[r];
    __shared__ float sv[ELL_CAP];
    __shared__ int   sc[ELL_CAP];
    if (b < n) { sv[b] = evals[r * ELL_CAP + b]; sc[b] = ecols[r * ELL_CAP + b]; }
    __syncthreads();
    float a0 = 0.0f, a1 = 0.0f;
    for (int j = 0; j < n; j++) {
        const float v = sv[j];
        const float2 y = *(const float2*)(Y + ((size_t)sc[j] * BATCH + b) * 2);
        a0 = fmaf(v, y.x, a0);
        a1 = fmaf(v, y.y, a1);
    }
    *(float2*)(out + ((size_t)b * NNODES + r) * 2) =
        make_float2(fmaxf(a0, 0.0f), fmaxf(a1, 0.0f));
}

// ---------------------------------------------------------------------------
// Launch
// ---------------------------------------------------------------------------
extern "C" void kernel_launch(void* const* d_in, const int* in_sizes, int n_in,
                              void* d_out, int out_size) {
    const float* H = (const float*)d_in[0];

    float *y, *sa, *evals, *rowsum;
    __nv_bfloat16 *xh, *xl, *uh, *ul, *wth, *wtl;
    int *ecols, *ecnt;
    cudaGetSymbolAddress((void**)&y,     g_y);
    cudaGetSymbolAddress((void**)&xh,    g_xh);
    cudaGetSymbolAddress((void**)&xl,    g_xl);
    cudaGetSymbolAddress((void**)&uh,    g_uh);
    cudaGetSymbolAddress((void**)&ul,    g_ul);
    cudaGetSymbolAddress((void**)&wth,   g_wth);
    cudaGetSymbolAddress((void**)&wtl,   g_wtl);
    cudaGetSymbolAddress((void**)&sa,    g_sa);
    cudaGetSymbolAddress((void**)&evals, g_ell_vals);
    cudaGetSymbolAddress((void**)&ecols, g_ell_cols);
    cudaGetSymbolAddress((void**)&ecnt,  g_ell_cnt);
    cudaGetSymbolAddress((void**)&rowsum, g_rowsum);

    const int SMEM_GEMM = NSTAGE * STAGE_B;   // 163840
    cudaFuncSetAttribute(gemm_bf16x3_mma<false>,
                         cudaFuncAttributeMaxDynamicSharedMemorySize, SMEM_GEMM);
    cudaFuncSetAttribute(gemm_bf16x3_mma<true>,
                         cudaFuncAttributeMaxDynamicSharedMemorySize, SMEM_GEMM);

    // Weight prep (one launch for all 4 tensor layers).
    {
        dim3 grid(500, 4);   // max N*Kp/256 = 400*320/256 = 500
        wt_split4_kernel<<<grid, 256>>>(
            (const float*)d_in[15], (const float*)d_in[17],
            (const float*)d_in[19], (const float*)d_in[21], wth, wtl);
    }

    zero_cnt_kernel<<<(4 * NNODES + 255) / 256, 256>>>(ecnt, 4 * NNODES);
    {
        dim3 grid((MAX_NNZ + 255) / 256, 4);
        ell_build4_kernel<<<grid, 256>>>(
            (const int*)d_in[1], (const int*)d_in[2], (const float*)d_in[3], in_sizes[1],
            (const int*)d_in[4], (const int*)d_in[5], (const float*)d_in[6], in_sizes[4],
            (const int*)d_in[7], (const int*)d_in[8], (const float*)d_in[9], in_sizes[7],
            (const int*)d_in[10], (const int*)d_in[11], (const float*)d_in[12], in_sizes[10],
            evals, ecols, ecnt);
    }
    rowsum_kernel<<<(4 * NNODES + 255) / 256, 256>>>(evals, ecnt, rowsum);

    #define EV(a) (evals + (size_t)(a) * NNODES * ELL_CAP)
    #define EC(a) (ecols + (size_t)(a) * NNODES * ELL_CAP)
    #define EN(a) (ecnt + (a) * NNODES)
    #define RS(a) (rowsum + (a) * NNODES)
    #define WH(t) (wth + (size_t)(t) * 400 * KP_MAX)
    #define WL(t) (wtl + (size_t)(t) * 400 * KP_MAX)

    // --- L0 (Form I, sm_s) ---
    spmm_in_kernel<<<NNODES, 256>>>(EV(0), EC(0), EN(0), H, sa);
    l0_proj_kernel<<<(MROWS * (KP_MAX / 4) + 255) / 256, 256>>>(
        sa, (const float*)d_in[13], (const float*)d_in[14], RS(0), xh, xl);

    // --- L1 (Form O, sm_s): GEMM -> Y[.,300]; spmm+relu+split -> Kp 320 ---
    gemm_bf16x3_mma<false><<<dim3(3, 510), 512, SMEM_GEMM>>>(
        xh, xl, WH(0), WL(0), (const float*)d_in[16], nullptr, y, nullptr, nullptr,
        300, 416, 0);
    {
        dim3 grid((BATCH * (320 / 4) + 255) / 256, NNODES);
        spmm_relu_split_kernel<<<grid, 256>>>(EV(0), EC(0), EN(0), y, 300, 320, xh, xl);
    }

    // --- L2 (Form O, sm_t): GEMM -> Y[.,100]; spmm+relu+split -> Kp 128 ---
    gemm_bf16x3_mma<false><<<dim3(1, 510), 512, SMEM_GEMM>>>(
        xh, xl, WH(1), WL(1), (const float*)d_in[18], nullptr, y, nullptr, nullptr,
        100, 320, 0);
    {
        dim3 grid((BATCH * (128 / 4) + 255) / 256, NNODES);
        spmm_relu_split_kernel<<<grid, 256>>>(EV(1), EC(1), EN(1), y, 100, 128, xh, xl);
    }

    // --- L3 (Form I, sp_t): spmm split->split (128); GEMM+relu+split -> 320 ---
    {
        dim3 grid((BATCH * (128 / 4) + 255) / 256, NNODES);
        spmm_ss_kernel<<<grid, 256>>>(EV(3), EC(3), EN(3), xh, xl, 128, uh, ul);
    }
    gemm_bf16x3_mma<true><<<dim3(3, 510), 512, SMEM_GEMM>>>(
        uh, ul, WH(2), WL(2), (const float*)d_in[20], RS(3), nullptr, xh, xl,
        300, 128, 320);

    // --- L4 (Form I, sp_s): spmm split->split (320); GEMM+relu+split -> 416 ---
    {
        dim3 grid((BATCH * (320 / 4) + 255) / 256, NNODES);
        spmm_ss_kernel<<<grid, 256>>>(EV(2), EC(2), EN(2), xh, xl, 320, uh, ul);
    }
    gemm_bf16x3_mma<true><<<dim3(4, 510), 512, SMEM_GEMM>>>(
        uh, ul, WH(3), WL(3), (const float*)d_in[22], RS(2), nullptr, xh, xl,
        400, 320, 416);

    // --- L5 (Form O, sp_s): narrow fp32 GEMM; fused spmm+relu+transpose ---
    l5_kernel<<<NNODES, 256>>>(xh, xl, (const float*)d_in[23], (const float*)d_in[24], sa);
    spmm_out_kernel<<<NNODES, 256>>>(EV(2), EC(2), EN(2), sa, (float*)d_out);
}